// round 4
// baseline (speedup 1.0000x reference)
#include <cuda_runtime.h>
#include <cuda_bf16.h>
#include <math_constants.h>
#include <cstdint>

#define M_ROWS 32768
#define DIMS   256
#define NCODES 1024
#define MAXCAND 24
#define MARGIN  8e-3f

#if defined(__CUDA_ARCH_FEAT_SM103_ALL) || defined(__CUDA_ARCH_FEAT_SM100_ALL) || defined(__CUDA_ARCH_FEAT_SM101_ALL)
#define HAS_TC 1
#else
#define HAS_TC 0
#endif

// ---------------- device-global scratch ------------------------------------
__device__ float g_z[M_ROWS * DIMS];
__device__ __align__(16) __nv_bfloat16 g_zb[M_ROWS * DIMS];
__device__ __align__(16) __nv_bfloat16 g_eb[NCODES * DIMS];
__device__ float g_cnorm[NCODES];
__device__ float g_rownorm[M_ROWS];
__device__ int   g_idx[M_ROWS];
__device__ float g_rowloss[M_ROWS];
__device__ int   g_cands[M_ROWS * MAXCAND];
__device__ float g_cdist[M_ROWS * MAXCAND];
__device__ int   g_ccount[M_ROWS];

// ---------------- PTX helpers (guarded: only exist in the 103a pass) --------
__device__ __forceinline__ uint32_t smem_u32(const void* p) {
    uint32_t a;
    asm("{ .reg .u64 t; cvta.to.shared.u64 t, %1; cvt.u32.u64 %0, t; }" : "=r"(a) : "l"(p));
    return a;
}
#define FENCE_ASYNC()    asm volatile("fence.proxy.async.shared::cta;" ::: "memory")
#define MBAR_INIT(mb, c) asm volatile("mbarrier.init.shared.b64 [%0], %1;" :: "r"(mb), "r"(c) : "memory")
#define MBAR_INVAL(mb)   asm volatile("mbarrier.inval.shared.b64 [%0];" :: "r"(mb) : "memory")
#define MBAR_WAIT(mb, ph) do {                                                 \
    uint32_t _m = (mb), _p = (ph), _d;                                         \
    asm volatile("{\n\t.reg .pred p;\n\t"                                      \
        "mbarrier.try_wait.parity.acquire.cta.shared::cta.b64 p, [%1], %2;\n\t"\
        "selp.b32 %0, 1, 0, p;\n\t}" : "=r"(_d) : "r"(_m), "r"(_p) : "memory");\
    if (!_d) {                                                                 \
        asm volatile("{\n\t.reg .pred P1;\n\tWL_%=:\n\t"                       \
            "mbarrier.try_wait.parity.acquire.cta.shared::cta.b64 P1, [%0], %1, 0x989680;\n\t" \
            "@P1 bra.uni WD_%=;\n\tbra.uni WL_%=;\n\tWD_%=:\n\t}"              \
            :: "r"(_m), "r"(_p) : "memory");                                   \
    }                                                                          \
} while (0)

#if HAS_TC
__device__ __forceinline__ uint32_t elect_one() {
    uint32_t p;
    asm volatile("{\n\t.reg .pred p;\n\telect.sync _|p, 0xFFFFFFFF;\n\t"
                 "selp.b32 %0, 1, 0, p;\n\t}" : "=r"(p));
    return p;
}
#define TC_ALLOC(sa, n)  asm volatile("tcgen05.alloc.cta_group::1.sync.aligned.shared::cta.b32 [%0], %1;" :: "r"(sa), "r"(n) : "memory")
#define TC_RELINQ()      asm volatile("tcgen05.relinquish_alloc_permit.cta_group::1.sync.aligned;")
#define TC_DEALLOC(t, n) asm volatile("tcgen05.dealloc.cta_group::1.sync.aligned.b32 %0, %1;" :: "r"(t), "r"(n))
#define TC_COMMIT(mb)    asm volatile("tcgen05.commit.cta_group::1.mbarrier::arrive::one.shared::cluster.b64 [%0];" :: "r"(mb) : "memory")
#define TC_WAIT_LD()     asm volatile("tcgen05.wait::ld.sync.aligned;" ::: "memory")
#define TC_FENCE_B()     asm volatile("tcgen05.fence::before_thread_sync;" ::: "memory")
#define TC_FENCE_A()     asm volatile("tcgen05.fence::after_thread_sync;" ::: "memory")

static constexpr uint64_t DESC_SW128 =
    (uint64_t(2) << 61) | (uint64_t(1) << 46) | (uint64_t(64) << 32) | (uint64_t(1) << 16);
__device__ __forceinline__ uint64_t make_desc(uint32_t a) {
    return DESC_SW128 | ((uint64_t)(a >> 4) & 0x3FFF);
}
__device__ __forceinline__ void mma_f16_ss(uint32_t d, uint64_t a, uint64_t b,
                                           uint32_t idesc, bool en) {
    uint32_t e = en ? 1u : 0u, z = 0u;
    asm volatile("{\n\t.reg .pred p;\n\tsetp.ne.u32 p, %5, 0;\n\t"
        "tcgen05.mma.cta_group::1.kind::f16 [%0], %1, %2, %3, {%4, %4, %4, %4}, p;\n\t}"
        :: "r"(d), "l"(a), "l"(b), "r"(idesc), "r"(z), "r"(e) : "memory");
}
__device__ __forceinline__ void ldtm32(uint32_t* r, uint32_t a) {
    asm volatile("tcgen05.ld.sync.aligned.32x32b.x32.b32 "
        "{%0,%1,%2,%3,%4,%5,%6,%7,%8,%9,%10,%11,%12,%13,%14,%15,"
        "%16,%17,%18,%19,%20,%21,%22,%23,%24,%25,%26,%27,%28,%29,%30,%31}, [%32];"
        : "=r"(r[0]),"=r"(r[1]),"=r"(r[2]),"=r"(r[3]),"=r"(r[4]),"=r"(r[5]),
          "=r"(r[6]),"=r"(r[7]),"=r"(r[8]),"=r"(r[9]),"=r"(r[10]),"=r"(r[11]),
          "=r"(r[12]),"=r"(r[13]),"=r"(r[14]),"=r"(r[15]),"=r"(r[16]),"=r"(r[17]),
          "=r"(r[18]),"=r"(r[19]),"=r"(r[20]),"=r"(r[21]),"=r"(r[22]),"=r"(r[23]),
          "=r"(r[24]),"=r"(r[25]),"=r"(r[26]),"=r"(r[27]),"=r"(r[28]),"=r"(r[29]),
          "=r"(r[30]),"=r"(r[31]) : "r"(a));
}
// idesc: F32 acc(1<<4), bf16 A(1<<7)/B(1<<10), N=128(16<<17), M=128(8<<24)
static constexpr uint32_t MMA_IDESC =
    (1u << 4) | (1u << 7) | (1u << 10) | (16u << 17) | (8u << 24);
#endif // HAS_TC

// ---------------- K1: z = x @ W^T + b ---------------------------------------
__global__ __launch_bounds__(256, 2)
void gemm_z_kernel(const float* __restrict__ x, const float* __restrict__ W,
                   const float* __restrict__ b)
{
    __shared__ float sA[8][128], sB[8][128];
    const int tid = threadIdx.x;
    const int rb = blockIdx.x * 128, cb = blockIdx.y * 128;
    const int tx = tid & 15, ty = tid >> 4;
    const int lr = tid >> 1, lk = (tid & 1) * 4;

    float acc[8][8];
#pragma unroll
    for (int i = 0; i < 8; i++)
#pragma unroll
        for (int j = 0; j < 8; j++) acc[i][j] = 0.f;

    for (int kb = 0; kb < DIMS; kb += 8) {
        float4 av = *reinterpret_cast<const float4*>(&x[(size_t)(rb + lr) * DIMS + kb + lk]);
        float4 bv = *reinterpret_cast<const float4*>(&W[(size_t)(cb + lr) * DIMS + kb + lk]);
        sA[lk+0][lr] = av.x; sA[lk+1][lr] = av.y; sA[lk+2][lr] = av.z; sA[lk+3][lr] = av.w;
        sB[lk+0][lr] = bv.x; sB[lk+1][lr] = bv.y; sB[lk+2][lr] = bv.z; sB[lk+3][lr] = bv.w;
        __syncthreads();
#pragma unroll
        for (int kk = 0; kk < 8; kk++) {
            float4 a0 = *reinterpret_cast<float4*>(&sA[kk][ty*8]);
            float4 a1 = *reinterpret_cast<float4*>(&sA[kk][ty*8+4]);
            float4 b0 = *reinterpret_cast<float4*>(&sB[kk][tx*8]);
            float4 b1 = *reinterpret_cast<float4*>(&sB[kk][tx*8+4]);
            float a[8] = {a0.x,a0.y,a0.z,a0.w,a1.x,a1.y,a1.z,a1.w};
            float e[8] = {b0.x,b0.y,b0.z,b0.w,b1.x,b1.y,b1.z,b1.w};
#pragma unroll
            for (int i = 0; i < 8; i++)
#pragma unroll
                for (int j = 0; j < 8; j++) acc[i][j] += a[i] * e[j];
        }
        __syncthreads();
    }
#pragma unroll
    for (int i = 0; i < 8; i++) {
        int r = rb + ty * 8 + i;
#pragma unroll
        for (int j = 0; j < 8; j += 4) {
            int c = cb + tx * 8 + j;
            float4 v;
            v.x = acc[i][j+0] + b[c+0]; v.y = acc[i][j+1] + b[c+1];
            v.z = acc[i][j+2] + b[c+2]; v.w = acc[i][j+3] + b[c+3];
            *reinterpret_cast<float4*>(&g_z[(size_t)r * DIMS + c]) = v;
            __nv_bfloat162 p0 = __floats2bfloat162_rn(v.x, v.y);
            __nv_bfloat162 p1 = __floats2bfloat162_rn(v.z, v.w);
            __nv_bfloat162* zp = reinterpret_cast<__nv_bfloat162*>(&g_zb[(size_t)r * DIMS + c]);
            zp[0] = p0; zp[1] = p1;
        }
    }
}

// ---------------- K2a: row norms ---------------------------------------------
__global__ void rownorm_kernel()
{
    int warp = (blockIdx.x * blockDim.x + threadIdx.x) >> 5;
    int lane = threadIdx.x & 31;
    if (warp >= M_ROWS) return;
    const float* p = &g_z[(size_t)warp * DIMS];
    float s = 0.f;
#pragma unroll
    for (int i = 0; i < 8; i++) { float v = p[lane + 32*i]; s += v*v; }
#pragma unroll
    for (int o = 16; o > 0; o >>= 1) s += __shfl_down_sync(0xffffffffu, s, o);
    if (lane == 0) g_rownorm[warp] = s;
}

// ---------------- K2b: emb -> bf16 + code norms ------------------------------
__global__ void conv_emb_kernel(const float* __restrict__ emb)
{
    int row = blockIdx.x * 8 + (threadIdx.x >> 5);
    int lane = threadIdx.x & 31;
    const float* p = &emb[(size_t)row * DIMS + lane * 8];
    float4 a = *reinterpret_cast<const float4*>(p);
    float4 c = *reinterpret_cast<const float4*>(p + 4);
    uint4 o;
    __nv_bfloat162 q;
    q = __floats2bfloat162_rn(a.x, a.y); o.x = *reinterpret_cast<uint32_t*>(&q);
    q = __floats2bfloat162_rn(a.z, a.w); o.y = *reinterpret_cast<uint32_t*>(&q);
    q = __floats2bfloat162_rn(c.x, c.y); o.z = *reinterpret_cast<uint32_t*>(&q);
    q = __floats2bfloat162_rn(c.z, c.w); o.w = *reinterpret_cast<uint32_t*>(&q);
    *reinterpret_cast<uint4*>(&g_eb[(size_t)row * DIMS + lane * 8]) = o;
    float s = a.x*a.x + a.y*a.y + a.z*a.z + a.w*a.w
            + c.x*c.x + c.y*c.y + c.z*c.z + c.w*c.w;
#pragma unroll
    for (int ofs = 16; ofs > 0; ofs >>= 1) s += __shfl_down_sync(0xffffffffu, s, ofs);
    if (lane == 0) g_cnorm[row] = s;
}

// ---------------- K3: tcgen05 coarse dist + candidate collection -------------
static constexpr uint32_t S_ZA = 0, S_EB0 = 65536, S_EB1 = 131072;
static constexpr uint32_t S_MBAR = 196608, S_TPTR = 196624;
static constexpr uint32_t SMEM_NEED = 196640 + 1024;

#if HAS_TC
// blocked atoms: 8 rows x 64 bf16 (1024B); atom_offset = atom_row + atom_col*16
__device__ __forceinline__ uint32_t tile_off(int row, int k) {
    uint32_t lin = (uint32_t)row * 128u + (uint32_t)(k >> 6) * 16384u + (uint32_t)(k & 63) * 2u;
    return lin ^ ((lin >> 3) & 0x70u);
}
__device__ __forceinline__ void load_tile(char* sm, uint32_t off,
                                          const __nv_bfloat16* src, int row0, int tid)
{
#pragma unroll
    for (int it = 0; it < 32; ++it) {
        int idx = it * 128 + tid;
        int row = idx >> 5;
        int k   = (idx & 31) << 3;
        *reinterpret_cast<uint4*>(sm + off + tile_off(row, k)) =
            *reinterpret_cast<const uint4*>(src + (size_t)(row0 + row) * DIMS + k);
    }
    FENCE_ASYNC();
}
__device__ __forceinline__ void epilogue_tile(uint32_t tbase, int nc, float rn,
                                              float& minv, int& cnt, int& ovf,
                                              size_t cbase)
{
#pragma unroll
    for (int c = 0; c < 4; ++c) {
        uint32_t regs[32];
        ldtm32(regs, tbase + c * 32);
        TC_WAIT_LD();
#pragma unroll
        for (int r = 0; r < 32; ++r) {
            int col = nc + c * 32 + r;
            float d = rn + g_cnorm[col] - 2.0f * __uint_as_float(regs[r]);
            if (d < minv) minv = d;
            if (d <= minv + MARGIN) {
                if (cnt == MAXCAND) {
                    int m = 0;
                    for (int k = 0; k < MAXCAND; k++) {
                        float dk = g_cdist[cbase + k];
                        if (dk <= minv + MARGIN) {
                            g_cands[cbase + m] = g_cands[cbase + k];
                            g_cdist[cbase + m] = dk; m++;
                        }
                    }
                    cnt = m;
                }
                if (cnt < MAXCAND) {
                    g_cands[cbase + cnt] = col; g_cdist[cbase + cnt] = d; cnt++;
                } else ovf = 1;
            }
        }
    }
}
#endif // HAS_TC

__global__ __launch_bounds__(128, 1)
void coarse_kernel()
{
#if HAS_TC
    extern __shared__ char smraw[];
    uint32_t raw = smem_u32(smraw);
    uint32_t sb  = (raw + 1023u) & ~1023u;
    char* sm = smraw + (sb - raw);

    const int tid = threadIdx.x, wid = tid >> 5, lane = tid & 31;
    const int rb  = blockIdx.x * 128;
    const int row = rb + wid * 32 + lane;
    const size_t cbase = (size_t)row * MAXCAND;

    if (wid == 0) TC_ALLOC(sb + S_TPTR, 256);
    if (tid == 0) { MBAR_INIT(sb + S_MBAR, 1); MBAR_INIT(sb + S_MBAR + 8, 1); }
    __syncthreads();
    uint32_t tmem;
    asm volatile("ld.shared.b32 %0, [%1];" : "=r"(tmem) : "r"(sb + S_TPTR));

    load_tile(sm, S_ZA, g_zb, rb, tid);
    __syncthreads();

    const float rn = g_rownorm[row];
    float minv = CUDART_INF_F;
    int cnt = 0, ovf = 0;
    const uint64_t a_base = make_desc(sb + S_ZA);

    for (int i = 0; i < 8; ++i) {
        const int buf = i & 1;
        load_tile(sm, buf ? S_EB1 : S_EB0, g_eb, i * 128, tid);
        __syncthreads();

        if (i >= 1) {
            const int pb = (i - 1) & 1;
            MBAR_WAIT(sb + S_MBAR + 8 * pb, ((i - 1) >> 1) & 1);
            TC_FENCE_A();
            epilogue_tile(tmem + pb * 128, (i - 1) * 128, rn, minv, cnt, ovf, cbase);
            TC_FENCE_B();
        }
        __syncthreads();

        if (wid == 0 && elect_one()) {
            TC_FENCE_A();
            uint64_t b_base = make_desc(sb + (buf ? S_EB1 : S_EB0));
            uint32_t dtm = tmem + buf * 128;
#pragma unroll
            for (int c = 0; c < 16; ++c) {
                uint64_t off = (uint64_t)((c >> 2) * 1024 + (c & 3) * 2);
                mma_f16_ss(dtm, a_base + off, b_base + off, MMA_IDESC, c > 0);
            }
            TC_COMMIT(sb + S_MBAR + 8 * buf);
        }
    }

    MBAR_WAIT(sb + S_MBAR + 8, 1);
    TC_FENCE_A();
    epilogue_tile(tmem + 128, 7 * 128, rn, minv, cnt, ovf, cbase);
    TC_FENCE_B();
    g_ccount[row] = ovf ? -1 : cnt;

    __syncthreads();
    if (tid == 0) { MBAR_INVAL(sb + S_MBAR); MBAR_INVAL(sb + S_MBAR + 8); }
    __syncthreads();
    if (wid == 0) { TC_RELINQ(); TC_DEALLOC(tmem, 256); }
#else
    // non-103a compile pass: mark every row for full exact scan (correct, slow;
    // never executed when the sm_103a cubin is loaded).
    g_ccount[blockIdx.x * 128 + threadIdx.x] = -1;
#endif
}

// ---------------- K4: exact fp32 recheck --------------------------------------
__global__ __launch_bounds__(256)
void recheck_kernel(const float* __restrict__ emb)
{
    int row  = blockIdx.x * 8 + (threadIdx.x >> 5);
    int lane = threadIdx.x & 31;
    int cnt  = g_ccount[row];

    const float* zp = &g_z[(size_t)row * DIMS];
    float zv[8];
#pragma unroll
    for (int i = 0; i < 8; i++) zv[i] = zp[lane + 32 * i];
    float rn = g_rownorm[row];

    float bv = CUDART_INF_F;
    int   bi = 0;
    if (cnt >= 0) {
        for (int c = 0; c < cnt; c++) {
            int idx = g_cands[(size_t)row * MAXCAND + c];
            const float* ep = &emb[(size_t)idx * DIMS];
            float dot = 0.f;
#pragma unroll
            for (int i = 0; i < 8; i++) dot += zv[i] * ep[lane + 32 * i];
#pragma unroll
            for (int o = 16; o > 0; o >>= 1) dot += __shfl_down_sync(0xffffffffu, dot, o);
            if (lane == 0) {
                float t = __fadd_rn(rn, g_cnorm[idx]);
                float dist = __fadd_rn(t, -__fmul_rn(2.0f, dot));
                if (dist < bv) { bv = dist; bi = idx; }
            }
        }
    } else {
        for (int idx = 0; idx < NCODES; idx++) {
            const float* ep = &emb[(size_t)idx * DIMS];
            float dot = 0.f;
#pragma unroll
            for (int i = 0; i < 8; i++) dot += zv[i] * ep[lane + 32 * i];
#pragma unroll
            for (int o = 16; o > 0; o >>= 1) dot += __shfl_down_sync(0xffffffffu, dot, o);
            if (lane == 0) {
                float t = __fadd_rn(rn, g_cnorm[idx]);
                float dist = __fadd_rn(t, -__fmul_rn(2.0f, dot));
                if (dist < bv) { bv = dist; bi = idx; }
            }
        }
    }
    if (lane == 0) g_idx[row] = bi;
}

// ---------------- K5: gather + per-row loss -----------------------------------
__global__ void gather_kernel(const float* __restrict__ emb,
                              float* __restrict__ outq, float* __restrict__ outi)
{
    __shared__ float ws[8];
    int row = blockIdx.x, d = threadIdx.x;
    int idx = g_idx[row];
    float e = emb[(size_t)idx * DIMS + d];
    float z = g_z[(size_t)row * DIMS + d];
    outq[(size_t)row * DIMS + d] = e;
    float diff = e - z;
    float s = diff * diff;
#pragma unroll
    for (int o = 16; o > 0; o >>= 1) s += __shfl_down_sync(0xffffffffu, s, o);
    int lane = d & 31, w = d >> 5;
    if (lane == 0) ws[w] = s;
    __syncthreads();
    if (d == 0) {
        float tot = 0.f;
#pragma unroll
        for (int i = 0; i < 8; i++) tot += ws[i];
        g_rowloss[row] = tot;
        outi[row] = (float)idx;
    }
}

// ---------------- K6: loss reduction ------------------------------------------
__global__ void loss_kernel(float* __restrict__ outl)
{
    __shared__ double sd[256];
    double s = 0.0;
    for (int i = threadIdx.x; i < M_ROWS; i += 256) s += (double)g_rowloss[i];
    sd[threadIdx.x] = s;
    __syncthreads();
    for (int o = 128; o > 0; o >>= 1) {
        if (threadIdx.x < o) sd[threadIdx.x] += sd[threadIdx.x + o];
        __syncthreads();
    }
    if (threadIdx.x == 0) outl[0] = (float)(1.25 * sd[0] / 8388608.0);
}

// ---------------- launch --------------------------------------------------------
extern "C" void kernel_launch(void* const* d_in, const int* in_sizes, int n_in,
                              void* d_out, int out_size)
{
    const float* x   = (const float*)d_in[0];
    const float* W   = (const float*)d_in[1];
    const float* b   = (const float*)d_in[2];
    const float* emb = (const float*)d_in[3];

    float* out  = (float*)d_out;
    float* outq = out;
    float* outi = out + (size_t)M_ROWS * DIMS;
    float* outl = outi + M_ROWS;

    static int smem_set = 0;
    if (!smem_set) {
        cudaFuncSetAttribute(coarse_kernel, cudaFuncAttributeMaxDynamicSharedMemorySize, SMEM_NEED);
        smem_set = 1;
    }

    dim3 g1(M_ROWS / 128, DIMS / 128);
    gemm_z_kernel<<<g1, 256>>>(x, W, b);
    rownorm_kernel<<<M_ROWS / 8, 256>>>();
    conv_emb_kernel<<<NCODES / 8, 256>>>(emb);
    coarse_kernel<<<M_ROWS / 128, 128, SMEM_NEED>>>();
    recheck_kernel<<<M_ROWS / 8, 256>>>(emb);
    gather_kernel<<<M_ROWS, 256>>>(emb, outq, outi);
    loss_kernel<<<1, 256>>>(outl);
}

// round 5
// speedup vs baseline: 2.3732x; 2.3732x over previous
#include <cuda_runtime.h>
#include <cuda_bf16.h>
#include <math_constants.h>
#include <cstdint>

#define M_ROWS 32768
#define DIMS   256
#define NCODES 1024
#define NCAND  8
#define MARGIN 2.5e-4f

#if defined(__CUDA_ARCH_FEAT_SM103_ALL) || defined(__CUDA_ARCH_FEAT_SM100_ALL) || defined(__CUDA_ARCH_FEAT_SM101_ALL)
#define HAS_TC 1
#else
#define HAS_TC 0
#endif

// ---------------- device-global scratch ------------------------------------
__device__ float g_z[M_ROWS * DIMS];
__device__ __align__(16) __nv_bfloat16 g_eh[NCODES * DIMS];
__device__ __align__(16) __nv_bfloat16 g_el[NCODES * DIMS];
__device__ float g_cnorm[NCODES];
__device__ float g_rownorm[M_ROWS];
__device__ int   g_idx[M_ROWS];
__device__ float g_rowloss[M_ROWS];
__device__ int   g_cands[M_ROWS * NCAND];
__device__ int   g_ccount[M_ROWS];

// ---------------- PTX helpers ------------------------------------------------
__device__ __forceinline__ uint32_t smem_u32(const void* p) {
    uint32_t a;
    asm("{ .reg .u64 t; cvta.to.shared.u64 t, %1; cvt.u32.u64 %0, t; }" : "=r"(a) : "l"(p));
    return a;
}
#define FENCE_ASYNC()    asm volatile("fence.proxy.async.shared::cta;" ::: "memory")
#define MBAR_INIT(mb, c) asm volatile("mbarrier.init.shared.b64 [%0], %1;" :: "r"(mb), "r"(c) : "memory")
#define MBAR_INVAL(mb)   asm volatile("mbarrier.inval.shared.b64 [%0];" :: "r"(mb) : "memory")
#define MBAR_WAIT(mb, ph) do {                                                 \
    uint32_t _m = (mb), _p = (ph), _d;                                         \
    asm volatile("{\n\t.reg .pred p;\n\t"                                      \
        "mbarrier.try_wait.parity.acquire.cta.shared::cta.b64 p, [%1], %2;\n\t"\
        "selp.b32 %0, 1, 0, p;\n\t}" : "=r"(_d) : "r"(_m), "r"(_p) : "memory");\
    if (!_d) {                                                                 \
        asm volatile("{\n\t.reg .pred P1;\n\tWL_%=:\n\t"                       \
            "mbarrier.try_wait.parity.acquire.cta.shared::cta.b64 P1, [%0], %1, 0x989680;\n\t" \
            "@P1 bra.uni WD_%=;\n\tbra.uni WL_%=;\n\tWD_%=:\n\t}"              \
            :: "r"(_m), "r"(_p) : "memory");                                   \
    }                                                                          \
} while (0)

#if HAS_TC
__device__ __forceinline__ uint32_t elect_one() {
    uint32_t p;
    asm volatile("{\n\t.reg .pred p;\n\telect.sync _|p, 0xFFFFFFFF;\n\t"
                 "selp.b32 %0, 1, 0, p;\n\t}" : "=r"(p));
    return p;
}
#define TC_ALLOC(sa, n)  asm volatile("tcgen05.alloc.cta_group::1.sync.aligned.shared::cta.b32 [%0], %1;" :: "r"(sa), "r"(n) : "memory")
#define TC_RELINQ()      asm volatile("tcgen05.relinquish_alloc_permit.cta_group::1.sync.aligned;")
#define TC_DEALLOC(t, n) asm volatile("tcgen05.dealloc.cta_group::1.sync.aligned.b32 %0, %1;" :: "r"(t), "r"(n))
#define TC_COMMIT(mb)    asm volatile("tcgen05.commit.cta_group::1.mbarrier::arrive::one.shared::cluster.b64 [%0];" :: "r"(mb) : "memory")
#define TC_WAIT_LD()     asm volatile("tcgen05.wait::ld.sync.aligned;" ::: "memory")
#define TC_WAIT_ST()     asm volatile("tcgen05.wait::st.sync.aligned;" ::: "memory")
#define TC_FENCE_B()     asm volatile("tcgen05.fence::before_thread_sync;" ::: "memory")
#define TC_FENCE_A()     asm volatile("tcgen05.fence::after_thread_sync;" ::: "memory")

static constexpr uint64_t DESC_SW128 =
    (uint64_t(2) << 61) | (uint64_t(1) << 46) | (uint64_t(64) << 32) | (uint64_t(1) << 16);
__device__ __forceinline__ uint64_t make_desc(uint32_t a) {
    return DESC_SW128 | ((uint64_t)(a >> 4) & 0x3FFF);
}
// TS-mode: A in TMEM, B via SMEM descriptor.
__device__ __forceinline__ void mma_f16_ts(uint32_t d, uint32_t a, uint64_t b,
                                           uint32_t idesc, bool en) {
    uint32_t e = en ? 1u : 0u, z = 0u;
    asm volatile("{\n\t.reg .pred p;\n\tsetp.ne.u32 p, %5, 0;\n\t"
        "tcgen05.mma.cta_group::1.kind::f16 [%0], [%1], %2, %3, {%4, %4, %4, %4}, p;\n\t}"
        :: "r"(d), "r"(a), "l"(b), "r"(idesc), "r"(z), "r"(e) : "memory");
}
__device__ __forceinline__ void ldtm32(uint32_t* r, uint32_t a) {
    asm volatile("tcgen05.ld.sync.aligned.32x32b.x32.b32 "
        "{%0,%1,%2,%3,%4,%5,%6,%7,%8,%9,%10,%11,%12,%13,%14,%15,"
        "%16,%17,%18,%19,%20,%21,%22,%23,%24,%25,%26,%27,%28,%29,%30,%31}, [%32];"
        : "=r"(r[0]),"=r"(r[1]),"=r"(r[2]),"=r"(r[3]),"=r"(r[4]),"=r"(r[5]),
          "=r"(r[6]),"=r"(r[7]),"=r"(r[8]),"=r"(r[9]),"=r"(r[10]),"=r"(r[11]),
          "=r"(r[12]),"=r"(r[13]),"=r"(r[14]),"=r"(r[15]),"=r"(r[16]),"=r"(r[17]),
          "=r"(r[18]),"=r"(r[19]),"=r"(r[20]),"=r"(r[21]),"=r"(r[22]),"=r"(r[23]),
          "=r"(r[24]),"=r"(r[25]),"=r"(r[26]),"=r"(r[27]),"=r"(r[28]),"=r"(r[29]),
          "=r"(r[30]),"=r"(r[31]) : "r"(a));
}
__device__ __forceinline__ void sttm32(uint32_t a, const uint32_t* r) {
    asm volatile("tcgen05.st.sync.aligned.32x32b.x32.b32 [%0], "
        "{%1,%2,%3,%4,%5,%6,%7,%8,%9,%10,%11,%12,%13,%14,%15,%16,"
        "%17,%18,%19,%20,%21,%22,%23,%24,%25,%26,%27,%28,%29,%30,%31,%32};"
        :: "r"(a),
           "r"(r[0]),"r"(r[1]),"r"(r[2]),"r"(r[3]),"r"(r[4]),"r"(r[5]),
           "r"(r[6]),"r"(r[7]),"r"(r[8]),"r"(r[9]),"r"(r[10]),"r"(r[11]),
           "r"(r[12]),"r"(r[13]),"r"(r[14]),"r"(r[15]),"r"(r[16]),"r"(r[17]),
           "r"(r[18]),"r"(r[19]),"r"(r[20]),"r"(r[21]),"r"(r[22]),"r"(r[23]),
           "r"(r[24]),"r"(r[25]),"r"(r[26]),"r"(r[27]),"r"(r[28]),"r"(r[29]),
           "r"(r[30]),"r"(r[31]) : "memory");
}
// idesc: F32 acc(1<<4), bf16 A(1<<7)/B(1<<10), N=64(8<<17), M=128(8<<24)
static constexpr uint32_t MMA_IDESC =
    (1u << 4) | (1u << 7) | (1u << 10) | (8u << 17) | (8u << 24);
#endif // HAS_TC

// ---------------- K1: z = x @ W^T + b ---------------------------------------
__global__ __launch_bounds__(256, 2)
void gemm_z_kernel(const float* __restrict__ x, const float* __restrict__ W,
                   const float* __restrict__ b)
{
    __shared__ float sA[8][128], sB[8][128];
    const int tid = threadIdx.x;
    const int rb = blockIdx.x * 128, cb = blockIdx.y * 128;
    const int tx = tid & 15, ty = tid >> 4;
    const int lr = tid >> 1, lk = (tid & 1) * 4;

    float acc[8][8];
#pragma unroll
    for (int i = 0; i < 8; i++)
#pragma unroll
        for (int j = 0; j < 8; j++) acc[i][j] = 0.f;

    for (int kb = 0; kb < DIMS; kb += 8) {
        float4 av = *reinterpret_cast<const float4*>(&x[(size_t)(rb + lr) * DIMS + kb + lk]);
        float4 bv = *reinterpret_cast<const float4*>(&W[(size_t)(cb + lr) * DIMS + kb + lk]);
        sA[lk+0][lr] = av.x; sA[lk+1][lr] = av.y; sA[lk+2][lr] = av.z; sA[lk+3][lr] = av.w;
        sB[lk+0][lr] = bv.x; sB[lk+1][lr] = bv.y; sB[lk+2][lr] = bv.z; sB[lk+3][lr] = bv.w;
        __syncthreads();
#pragma unroll
        for (int kk = 0; kk < 8; kk++) {
            float4 a0 = *reinterpret_cast<float4*>(&sA[kk][ty*8]);
            float4 a1 = *reinterpret_cast<float4*>(&sA[kk][ty*8+4]);
            float4 b0 = *reinterpret_cast<float4*>(&sB[kk][tx*8]);
            float4 b1 = *reinterpret_cast<float4*>(&sB[kk][tx*8+4]);
            float a[8] = {a0.x,a0.y,a0.z,a0.w,a1.x,a1.y,a1.z,a1.w};
            float e[8] = {b0.x,b0.y,b0.z,b0.w,b1.x,b1.y,b1.z,b1.w};
#pragma unroll
            for (int i = 0; i < 8; i++)
#pragma unroll
                for (int j = 0; j < 8; j++) acc[i][j] += a[i] * e[j];
        }
        __syncthreads();
    }
#pragma unroll
    for (int i = 0; i < 8; i++) {
        int r = rb + ty * 8 + i;
#pragma unroll
        for (int j = 0; j < 8; j += 4) {
            int c = cb + tx * 8 + j;
            float4 v;
            v.x = acc[i][j+0] + b[c+0]; v.y = acc[i][j+1] + b[c+1];
            v.z = acc[i][j+2] + b[c+2]; v.w = acc[i][j+3] + b[c+3];
            *reinterpret_cast<float4*>(&g_z[(size_t)r * DIMS + c]) = v;
        }
    }
}

// ---------------- K2a: row norms ---------------------------------------------
__global__ void rownorm_kernel()
{
    int warp = (blockIdx.x * blockDim.x + threadIdx.x) >> 5;
    int lane = threadIdx.x & 31;
    if (warp >= M_ROWS) return;
    const float* p = &g_z[(size_t)warp * DIMS];
    float s = 0.f;
#pragma unroll
    for (int i = 0; i < 8; i++) { float v = p[lane + 32*i]; s += v*v; }
#pragma unroll
    for (int o = 16; o > 0; o >>= 1) s += __shfl_down_sync(0xffffffffu, s, o);
    if (lane == 0) g_rownorm[warp] = s;
}

// ---------------- K2b: emb -> split bf16 + code norms ------------------------
__global__ void conv_emb_kernel(const float* __restrict__ emb)
{
    int row = blockIdx.x * 8 + (threadIdx.x >> 5);
    int lane = threadIdx.x & 31;
    const float* p = &emb[(size_t)row * DIMS + lane * 8];
    float v[8];
    *reinterpret_cast<float4*>(v)     = *reinterpret_cast<const float4*>(p);
    *reinterpret_cast<float4*>(v + 4) = *reinterpret_cast<const float4*>(p + 4);
    uint4 oh, ol;
    uint32_t* ohp = reinterpret_cast<uint32_t*>(&oh);
    uint32_t* olp = reinterpret_cast<uint32_t*>(&ol);
    float s = 0.f;
#pragma unroll
    for (int j = 0; j < 4; j++) {
        float a0 = v[2*j], a1 = v[2*j+1];
        __nv_bfloat16 h0 = __float2bfloat16(a0), h1 = __float2bfloat16(a1);
        float r0 = a0 - __bfloat162float(h0), r1 = a1 - __bfloat162float(h1);
        __nv_bfloat162 hp; hp.x = h0; hp.y = h1;
        __nv_bfloat162 lp = __floats2bfloat162_rn(r0, r1);
        ohp[j] = *reinterpret_cast<uint32_t*>(&hp);
        olp[j] = *reinterpret_cast<uint32_t*>(&lp);
        s += a0*a0 + a1*a1;
    }
    *reinterpret_cast<uint4*>(&g_eh[(size_t)row * DIMS + lane * 8]) = oh;
    *reinterpret_cast<uint4*>(&g_el[(size_t)row * DIMS + lane * 8]) = ol;
#pragma unroll
    for (int ofs = 16; ofs > 0; ofs >>= 1) s += __shfl_down_sync(0xffffffffu, s, ofs);
    if (lane == 0) g_cnorm[row] = s;
}

// ---------------- K3: split-bf16 tcgen05 coarse argmin -----------------------
// SMEM: 4 B-buffers (hi0,lo0 | hi1,lo1) 128KB, cnorm 4KB, mbar, tmem ptr.
static constexpr uint32_t S_B = 0, S_CN = 131072, S_MB = 135168, S_TP = 135184;
static constexpr uint32_t SMEM_NEED = 135188 + 1024 + 12;

#if HAS_TC
__device__ __forceinline__ uint32_t toff(int r, int k) {
    uint32_t lin = (uint32_t)(r >> 3) * 1024u + (uint32_t)(k >> 6) * 8192u
                 + (uint32_t)(r & 7) * 128u + (uint32_t)(k & 63) * 2u;
    return lin ^ ((lin >> 3) & 0x70u);
}
__device__ __forceinline__ void load_btile(char* sm, int buf, int tile, int tid)
{
    const __nv_bfloat16* eh = g_eh + (size_t)tile * 64 * DIMS;
    const __nv_bfloat16* el = g_el + (size_t)tile * 64 * DIMS;
    uint32_t base = S_B + (uint32_t)buf * 65536u;
#pragma unroll
    for (int l = 0; l < 16; ++l) {
        int idx = l * 128 + tid;
        int r = idx >> 5, k = (idx & 31) << 3;
        uint32_t o = toff(r, k);
        *reinterpret_cast<uint4*>(sm + base + o) =
            *reinterpret_cast<const uint4*>(eh + r * DIMS + k);
        *reinterpret_cast<uint4*>(sm + base + 32768u + o) =
            *reinterpret_cast<const uint4*>(el + r * DIMS + k);
    }
    FENCE_ASYNC();
}
#endif

__global__ __launch_bounds__(128, 1)
void coarse_kernel()
{
#if HAS_TC
    extern __shared__ char smraw[];
    uint32_t raw = smem_u32(smraw);
    uint32_t sb  = (raw + 1023u) & ~1023u;
    char* sm = smraw + (sb - raw);
    float* scn   = reinterpret_cast<float*>(sm + S_CN);
    float* stage = reinterpret_cast<float*>(sm + S_B);   // reused before B loads

    const int tid = threadIdx.x;
    const int rb  = blockIdx.x * 128;
    const int row = rb + tid;

    if (tid < 32) TC_ALLOC(sb + S_TP, 512);
    if (tid == 0) { MBAR_INIT(sb + S_MB, 1); MBAR_INIT(sb + S_MB + 8, 1); }
    for (int i = tid; i < NCODES; i += 128) scn[i] = g_cnorm[i];
    __syncthreads();
    uint32_t tmem;
    asm volatile("ld.shared.b32 %0, [%1];" : "=r"(tmem) : "r"(sb + S_TP));
    const uint32_t woff = ((uint32_t)tid >> 5) << 21;

    // ---- stage z -> TMEM A (hi at cols 0-127, lo at 128-255) ----
    for (int ch = 0; ch < 4; ++ch) {
#pragma unroll
        for (int l = 0; l < 16; ++l) {
            int idx = l * 128 + tid;
            int r = idx >> 4, c4 = idx & 15;
            *reinterpret_cast<float4*>(stage + r * 68 + c4 * 4) =
                *reinterpret_cast<const float4*>(&g_z[(size_t)(rb + r) * DIMS + ch * 64 + c4 * 4]);
        }
        __syncthreads();
        uint32_t hi[32], lo[32];
#pragma unroll
        for (int j = 0; j < 32; ++j) {
            float a0 = stage[tid * 68 + 2*j], a1 = stage[tid * 68 + 2*j + 1];
            __nv_bfloat16 h0 = __float2bfloat16(a0), h1 = __float2bfloat16(a1);
            float r0 = a0 - __bfloat162float(h0), r1 = a1 - __bfloat162float(h1);
            __nv_bfloat162 hp; hp.x = h0; hp.y = h1;
            __nv_bfloat162 lp = __floats2bfloat162_rn(r0, r1);
            hi[j] = *reinterpret_cast<uint32_t*>(&hp);
            lo[j] = *reinterpret_cast<uint32_t*>(&lp);
        }
        sttm32(tmem +       ch * 32 + woff, hi);
        sttm32(tmem + 128 + ch * 32 + woff, lo);
        TC_WAIT_ST();
        __syncthreads();
    }

    load_btile(sm, 0, 0, tid);
    __syncthreads();

    const float rn = g_rownorm[row];
    float min1 = CUDART_INF_F, min2 = CUDART_INF_F;
    int idx1 = 0;
    int cand[NCAND]; float cdv[NCAND];
    int cnt = 0, ovf = 0;

    for (int i = 0; i < 16; ++i) {
        const int buf = i & 1;
        if (tid < 32 && elect_one()) {
            TC_FENCE_A();
            uint64_t bh = make_desc(sb + S_B + (uint32_t)buf * 65536u);
            uint64_t bl = bh + (32768u >> 4);
            uint32_t D  = tmem + 256 + buf * 64;
#pragma unroll
            for (int c = 0; c < 16; ++c) {
                uint64_t off = (uint64_t)((c >> 2) * 512 + (c & 3) * 2);
                uint32_t ah = tmem + c * 8, al = tmem + 128 + c * 8;
                mma_f16_ts(D, ah, bh + off, MMA_IDESC, c > 0);
                mma_f16_ts(D, ah, bl + off, MMA_IDESC, true);
                mma_f16_ts(D, al, bh + off, MMA_IDESC, true);
            }
            TC_COMMIT(sb + S_MB + 8 * buf);
        }
        if (i >= 1) {
            MBAR_WAIT(sb + S_MB + 8 * (buf ^ 1), ((i - 1) >> 1) & 1);
            TC_FENCE_A();
        }
        if (i < 15) load_btile(sm, buf ^ 1, i + 1, tid);
        if (i >= 1) {
            const int col0 = (i - 1) * 64;
            const uint32_t Dp = tmem + 256 + (buf ^ 1) * 64;
#pragma unroll
            for (int h = 0; h < 2; ++h) {
                uint32_t regs[32];
                ldtm32(regs, Dp + h * 32);
                TC_WAIT_LD();
#pragma unroll
                for (int r = 0; r < 32; ++r) {
                    int col = col0 + h * 32 + r;
                    float d = __fadd_rn(rn, scn[col]) - 2.0f * __uint_as_float(regs[r]);
                    bool lt = d < min1;
                    min2 = fminf(min2, lt ? min1 : d);
                    if (lt) { min1 = d; idx1 = col; }
                    if (d <= min1 + MARGIN) {
                        if (cnt == NCAND) {
                            int m = 0;
#pragma unroll
                            for (int k = 0; k < NCAND; k++)
                                if (cdv[k] <= min1 + MARGIN) { cand[m] = cand[k]; cdv[m] = cdv[k]; m++; }
                            cnt = m;
                        }
                        if (cnt < NCAND) { cand[cnt] = col; cdv[cnt] = d; cnt++; }
                        else ovf = 1;
                    }
                }
            }
            TC_FENCE_B();
        }
        __syncthreads();
    }
    MBAR_WAIT(sb + S_MB + 8, 1);
    TC_FENCE_A();
    {
        const int col0 = 15 * 64;
        const uint32_t Dp = tmem + 256 + 64;
#pragma unroll
        for (int h = 0; h < 2; ++h) {
            uint32_t regs[32];
            ldtm32(regs, Dp + h * 32);
            TC_WAIT_LD();
#pragma unroll
            for (int r = 0; r < 32; ++r) {
                int col = col0 + h * 32 + r;
                float d = __fadd_rn(rn, scn[col]) - 2.0f * __uint_as_float(regs[r]);
                bool lt = d < min1;
                min2 = fminf(min2, lt ? min1 : d);
                if (lt) { min1 = d; idx1 = col; }
                if (d <= min1 + MARGIN) {
                    if (cnt == NCAND) {
                        int m = 0;
#pragma unroll
                        for (int k = 0; k < NCAND; k++)
                            if (cdv[k] <= min1 + MARGIN) { cand[m] = cand[k]; cdv[m] = cdv[k]; m++; }
                        cnt = m;
                    }
                    if (cnt < NCAND) { cand[cnt] = col; cdv[cnt] = d; cnt++; }
                    else ovf = 1;
                }
            }
        }
    }
    TC_FENCE_B();

    // final compaction + verdict
    g_idx[row] = idx1;
    if (ovf) {
        g_ccount[row] = -1;
    } else {
        int m = 0;
#pragma unroll
        for (int k = 0; k < NCAND; k++)
            if (k < cnt && cdv[k] <= min1 + MARGIN) { cand[m] = cand[k]; m++; }
        if (m <= 1) {
            g_ccount[row] = 0;                 // decided: idx1 is exact argmin
        } else {
            for (int k = 0; k < m; k++) g_cands[(size_t)row * NCAND + k] = cand[k];
            g_ccount[row] = m;
        }
    }

    __syncthreads();
    if (tid == 0) { MBAR_INVAL(sb + S_MB); MBAR_INVAL(sb + S_MB + 8); }
    __syncthreads();
    if (tid < 32) { TC_RELINQ(); TC_DEALLOC(tmem, 512); }
#else
    g_ccount[blockIdx.x * 128 + threadIdx.x] = -1;   // fallback pass: full scan
#endif
}

// ---------------- K4: exact fp32 recheck (reference rounding) ----------------
__global__ __launch_bounds__(256)
void recheck_kernel(const float* __restrict__ emb)
{
    int row  = blockIdx.x * 8 + (threadIdx.x >> 5);
    int lane = threadIdx.x & 31;
    int cnt  = g_ccount[row];
    if (cnt == 0) return;

    const float* zp = &g_z[(size_t)row * DIMS];
    float zv[8];
#pragma unroll
    for (int i = 0; i < 8; i++) zv[i] = zp[lane + 32 * i];
    float rn = g_rownorm[row];

    float bv = CUDART_INF_F;
    int   bi = 0;
    if (cnt > 0) {
        for (int c = 0; c < cnt; c++) {
            int idx = g_cands[(size_t)row * NCAND + c];
            const float* ep = &emb[(size_t)idx * DIMS];
            float dot = 0.f;
#pragma unroll
            for (int i = 0; i < 8; i++) dot += zv[i] * ep[lane + 32 * i];
#pragma unroll
            for (int o = 16; o > 0; o >>= 1) dot += __shfl_down_sync(0xffffffffu, dot, o);
            if (lane == 0) {
                float t = __fadd_rn(rn, g_cnorm[idx]);
                float dist = __fadd_rn(t, -__fmul_rn(2.0f, dot));
                if (dist < bv) { bv = dist; bi = idx; }
            }
        }
    } else {
        for (int idx = 0; idx < NCODES; idx++) {
            const float* ep = &emb[(size_t)idx * DIMS];
            float dot = 0.f;
#pragma unroll
            for (int i = 0; i < 8; i++) dot += zv[i] * ep[lane + 32 * i];
#pragma unroll
            for (int o = 16; o > 0; o >>= 1) dot += __shfl_down_sync(0xffffffffu, dot, o);
            if (lane == 0) {
                float t = __fadd_rn(rn, g_cnorm[idx]);
                float dist = __fadd_rn(t, -__fmul_rn(2.0f, dot));
                if (dist < bv) { bv = dist; bi = idx; }
            }
        }
    }
    if (lane == 0) g_idx[row] = bi;
}

// ---------------- K5: gather + per-row loss -----------------------------------
__global__ void gather_kernel(const float* __restrict__ emb,
                              float* __restrict__ outq, float* __restrict__ outi)
{
    __shared__ float ws[8];
    int row = blockIdx.x, d = threadIdx.x;
    int idx = g_idx[row];
    float e = emb[(size_t)idx * DIMS + d];
    float z = g_z[(size_t)row * DIMS + d];
    outq[(size_t)row * DIMS + d] = e;
    float diff = e - z;
    float s = diff * diff;
#pragma unroll
    for (int o = 16; o > 0; o >>= 1) s += __shfl_down_sync(0xffffffffu, s, o);
    int lane = d & 31, w = d >> 5;
    if (lane == 0) ws[w] = s;
    __syncthreads();
    if (d == 0) {
        float tot = 0.f;
#pragma unroll
        for (int i = 0; i < 8; i++) tot += ws[i];
        g_rowloss[row] = tot;
        outi[row] = (float)idx;
    }
}

// ---------------- K6: loss reduction ------------------------------------------
__global__ void loss_kernel(float* __restrict__ outl)
{
    __shared__ double sd[256];
    double s = 0.0;
    for (int i = threadIdx.x; i < M_ROWS; i += 256) s += (double)g_rowloss[i];
    sd[threadIdx.x] = s;
    __syncthreads();
    for (int o = 128; o > 0; o >>= 1) {
        if (threadIdx.x < o) sd[threadIdx.x] += sd[threadIdx.x + o];
        __syncthreads();
    }
    if (threadIdx.x == 0) outl[0] = (float)(1.25 * sd[0] / 8388608.0);
}

// ---------------- launch --------------------------------------------------------
extern "C" void kernel_launch(void* const* d_in, const int* in_sizes, int n_in,
                              void* d_out, int out_size)
{
    const float* x   = (const float*)d_in[0];
    const float* W   = (const float*)d_in[1];
    const float* b   = (const float*)d_in[2];
    const float* emb = (const float*)d_in[3];

    float* out  = (float*)d_out;
    float* outq = out;
    float* outi = out + (size_t)M_ROWS * DIMS;
    float* outl = outi + M_ROWS;

    static int smem_set = 0;
    if (!smem_set) {
        cudaFuncSetAttribute(coarse_kernel, cudaFuncAttributeMaxDynamicSharedMemorySize, SMEM_NEED);
        smem_set = 1;
    }

    dim3 g1(M_ROWS / 128, DIMS / 128);
    gemm_z_kernel<<<g1, 256>>>(x, W, b);
    rownorm_kernel<<<M_ROWS / 8, 256>>>();
    conv_emb_kernel<<<NCODES / 8, 256>>>(emb);
    coarse_kernel<<<M_ROWS / 128, 128, SMEM_NEED>>>();
    recheck_kernel<<<M_ROWS / 8, 256>>>(emb);
    gather_kernel<<<M_ROWS, 256>>>(emb, outq, outi);
    loss_kernel<<<1, 256>>>(outl);
}

// round 6
// speedup vs baseline: 3.2777x; 1.3811x over previous
#include <cuda_runtime.h>
#include <cuda_bf16.h>
#include <math_constants.h>
#include <cstdint>

#define M_ROWS 32768
#define DIMS   256
#define NCODES 1024
#define NCAND  8
#define MARGIN 2.5e-4f

#if defined(__CUDA_ARCH_FEAT_SM103_ALL) || defined(__CUDA_ARCH_FEAT_SM100_ALL) || defined(__CUDA_ARCH_FEAT_SM101_ALL)
#define HAS_TC 1
#else
#define HAS_TC 0
#endif

// ---------------- device-global scratch ------------------------------------
__device__ float g_z[M_ROWS * DIMS];
__device__ __align__(16) __nv_bfloat16 g_eh[NCODES * DIMS];
__device__ __align__(16) __nv_bfloat16 g_el[NCODES * DIMS];
__device__ float g_cnorm[NCODES];
__device__ float g_rownorm[M_ROWS];
__device__ int   g_idx[M_ROWS];
__device__ float g_rowloss[M_ROWS];
__device__ int   g_cands[M_ROWS * NCAND];
__device__ int   g_ccount[M_ROWS];

// ---------------- PTX helpers ------------------------------------------------
__device__ __forceinline__ uint32_t smem_u32(const void* p) {
    uint32_t a;
    asm("{ .reg .u64 t; cvta.to.shared.u64 t, %1; cvt.u32.u64 %0, t; }" : "=r"(a) : "l"(p));
    return a;
}
#define CP_ASYNC16(s, g) asm volatile("cp.async.cg.shared.global [%0], [%1], 16;" :: "r"(s), "l"(g) : "memory")
#define CP_COMMIT()      asm volatile("cp.async.commit_group;" ::: "memory")
#define CP_WAIT0()       asm volatile("cp.async.wait_group 0;" ::: "memory")
#define MBAR_INIT(mb, c) asm volatile("mbarrier.init.shared.b64 [%0], %1;" :: "r"(mb), "r"(c) : "memory")
#define MBAR_INVAL(mb)   asm volatile("mbarrier.inval.shared.b64 [%0];" :: "r"(mb) : "memory")
#define MBAR_WAIT(mb, ph) do {                                                 \
    uint32_t _m = (mb), _p = (ph), _d;                                         \
    asm volatile("{\n\t.reg .pred p;\n\t"                                      \
        "mbarrier.try_wait.parity.acquire.cta.shared::cta.b64 p, [%1], %2;\n\t"\
        "selp.b32 %0, 1, 0, p;\n\t}" : "=r"(_d) : "r"(_m), "r"(_p) : "memory");\
    if (!_d) {                                                                 \
        asm volatile("{\n\t.reg .pred P1;\n\tWL_%=:\n\t"                       \
            "mbarrier.try_wait.parity.acquire.cta.shared::cta.b64 P1, [%0], %1, 0x989680;\n\t" \
            "@P1 bra.uni WD_%=;\n\tbra.uni WL_%=;\n\tWD_%=:\n\t}"              \
            :: "r"(_m), "r"(_p) : "memory");                                   \
    }                                                                          \
} while (0)

#if HAS_TC
__device__ __forceinline__ uint32_t elect_one() {
    uint32_t p;
    asm volatile("{\n\t.reg .pred p;\n\telect.sync _|p, 0xFFFFFFFF;\n\t"
                 "selp.b32 %0, 1, 0, p;\n\t}" : "=r"(p));
    return p;
}
#define TC_ALLOC(sa, n)  asm volatile("tcgen05.alloc.cta_group::1.sync.aligned.shared::cta.b32 [%0], %1;" :: "r"(sa), "r"(n) : "memory")
#define TC_RELINQ()      asm volatile("tcgen05.relinquish_alloc_permit.cta_group::1.sync.aligned;")
#define TC_DEALLOC(t, n) asm volatile("tcgen05.dealloc.cta_group::1.sync.aligned.b32 %0, %1;" :: "r"(t), "r"(n))
#define TC_COMMIT(mb)    asm volatile("tcgen05.commit.cta_group::1.mbarrier::arrive::one.shared::cluster.b64 [%0];" :: "r"(mb) : "memory")
#define TC_WAIT_LD()     asm volatile("tcgen05.wait::ld.sync.aligned;" ::: "memory")
#define TC_WAIT_ST()     asm volatile("tcgen05.wait::st.sync.aligned;" ::: "memory")
#define TC_FENCE_B()     asm volatile("tcgen05.fence::before_thread_sync;" ::: "memory")
#define TC_FENCE_A()     asm volatile("tcgen05.fence::after_thread_sync;" ::: "memory")

static constexpr uint64_t DESC_SW128 =
    (uint64_t(2) << 61) | (uint64_t(1) << 46) | (uint64_t(64) << 32) | (uint64_t(1) << 16);
__device__ __forceinline__ uint64_t make_desc(uint32_t a) {
    return DESC_SW128 | ((uint64_t)(a >> 4) & 0x3FFF);
}
__device__ __forceinline__ void mma_f16_ts(uint32_t d, uint32_t a, uint64_t b,
                                           uint32_t idesc, bool en) {
    uint32_t e = en ? 1u : 0u, z = 0u;
    asm volatile("{\n\t.reg .pred p;\n\tsetp.ne.u32 p, %5, 0;\n\t"
        "tcgen05.mma.cta_group::1.kind::f16 [%0], [%1], %2, %3, {%4, %4, %4, %4}, p;\n\t}"
        :: "r"(d), "r"(a), "l"(b), "r"(idesc), "r"(z), "r"(e) : "memory");
}
__device__ __forceinline__ void ldtm32(uint32_t* r, uint32_t a) {
    asm volatile("tcgen05.ld.sync.aligned.32x32b.x32.b32 "
        "{%0,%1,%2,%3,%4,%5,%6,%7,%8,%9,%10,%11,%12,%13,%14,%15,"
        "%16,%17,%18,%19,%20,%21,%22,%23,%24,%25,%26,%27,%28,%29,%30,%31}, [%32];"
        : "=r"(r[0]),"=r"(r[1]),"=r"(r[2]),"=r"(r[3]),"=r"(r[4]),"=r"(r[5]),
          "=r"(r[6]),"=r"(r[7]),"=r"(r[8]),"=r"(r[9]),"=r"(r[10]),"=r"(r[11]),
          "=r"(r[12]),"=r"(r[13]),"=r"(r[14]),"=r"(r[15]),"=r"(r[16]),"=r"(r[17]),
          "=r"(r[18]),"=r"(r[19]),"=r"(r[20]),"=r"(r[21]),"=r"(r[22]),"=r"(r[23]),
          "=r"(r[24]),"=r"(r[25]),"=r"(r[26]),"=r"(r[27]),"=r"(r[28]),"=r"(r[29]),
          "=r"(r[30]),"=r"(r[31]) : "r"(a));
}
__device__ __forceinline__ void sttm32(uint32_t a, const uint32_t* r) {
    asm volatile("tcgen05.st.sync.aligned.32x32b.x32.b32 [%0], "
        "{%1,%2,%3,%4,%5,%6,%7,%8,%9,%10,%11,%12,%13,%14,%15,%16,"
        "%17,%18,%19,%20,%21,%22,%23,%24,%25,%26,%27,%28,%29,%30,%31,%32};"
        :: "r"(a),
           "r"(r[0]),"r"(r[1]),"r"(r[2]),"r"(r[3]),"r"(r[4]),"r"(r[5]),
           "r"(r[6]),"r"(r[7]),"r"(r[8]),"r"(r[9]),"r"(r[10]),"r"(r[11]),
           "r"(r[12]),"r"(r[13]),"r"(r[14]),"r"(r[15]),"r"(r[16]),"r"(r[17]),
           "r"(r[18]),"r"(r[19]),"r"(r[20]),"r"(r[21]),"r"(r[22]),"r"(r[23]),
           "r"(r[24]),"r"(r[25]),"r"(r[26]),"r"(r[27]),"r"(r[28]),"r"(r[29]),
           "r"(r[30]),"r"(r[31]) : "memory");
}
// idesc: F32 acc(1<<4), bf16 A(1<<7)/B(1<<10), N=64(8<<17), M=128(8<<24)
static constexpr uint32_t MMA_IDESC =
    (1u << 4) | (1u << 7) | (1u << 10) | (8u << 17) | (8u << 24);
#endif // HAS_TC

// ---------------- K1: z = x @ W^T + b (fp32 exact) ---------------------------
__global__ __launch_bounds__(256, 2)
void gemm_z_kernel(const float* __restrict__ x, const float* __restrict__ W,
                   const float* __restrict__ b)
{
    __shared__ float sA[8][128], sB[8][128];
    const int tid = threadIdx.x;
    const int rb = blockIdx.x * 128, cb = blockIdx.y * 128;
    const int tx = tid & 15, ty = tid >> 4;
    const int lr = tid >> 1, lk = (tid & 1) * 4;

    float acc[8][8];
#pragma unroll
    for (int i = 0; i < 8; i++)
#pragma unroll
        for (int j = 0; j < 8; j++) acc[i][j] = 0.f;

    for (int kb = 0; kb < DIMS; kb += 8) {
        float4 av = *reinterpret_cast<const float4*>(&x[(size_t)(rb + lr) * DIMS + kb + lk]);
        float4 bv = *reinterpret_cast<const float4*>(&W[(size_t)(cb + lr) * DIMS + kb + lk]);
        sA[lk+0][lr] = av.x; sA[lk+1][lr] = av.y; sA[lk+2][lr] = av.z; sA[lk+3][lr] = av.w;
        sB[lk+0][lr] = bv.x; sB[lk+1][lr] = bv.y; sB[lk+2][lr] = bv.z; sB[lk+3][lr] = bv.w;
        __syncthreads();
#pragma unroll
        for (int kk = 0; kk < 8; kk++) {
            float4 a0 = *reinterpret_cast<float4*>(&sA[kk][ty*8]);
            float4 a1 = *reinterpret_cast<float4*>(&sA[kk][ty*8+4]);
            float4 b0 = *reinterpret_cast<float4*>(&sB[kk][tx*8]);
            float4 b1 = *reinterpret_cast<float4*>(&sB[kk][tx*8+4]);
            float a[8] = {a0.x,a0.y,a0.z,a0.w,a1.x,a1.y,a1.z,a1.w};
            float e[8] = {b0.x,b0.y,b0.z,b0.w,b1.x,b1.y,b1.z,b1.w};
#pragma unroll
            for (int i = 0; i < 8; i++)
#pragma unroll
                for (int j = 0; j < 8; j++) acc[i][j] += a[i] * e[j];
        }
        __syncthreads();
    }
#pragma unroll
    for (int i = 0; i < 8; i++) {
        int r = rb + ty * 8 + i;
#pragma unroll
        for (int j = 0; j < 8; j += 4) {
            int c = cb + tx * 8 + j;
            float4 v;
            v.x = acc[i][j+0] + b[c+0]; v.y = acc[i][j+1] + b[c+1];
            v.z = acc[i][j+2] + b[c+2]; v.w = acc[i][j+3] + b[c+3];
            *reinterpret_cast<float4*>(&g_z[(size_t)r * DIMS + c]) = v;
        }
    }
}

// ---------------- K2: emb -> split bf16 + code norms -------------------------
__global__ void conv_emb_kernel(const float* __restrict__ emb)
{
    int row = blockIdx.x * 8 + (threadIdx.x >> 5);
    int lane = threadIdx.x & 31;
    const float* p = &emb[(size_t)row * DIMS + lane * 8];
    float v[8];
    *reinterpret_cast<float4*>(v)     = *reinterpret_cast<const float4*>(p);
    *reinterpret_cast<float4*>(v + 4) = *reinterpret_cast<const float4*>(p + 4);
    uint4 oh, ol;
    uint32_t* ohp = reinterpret_cast<uint32_t*>(&oh);
    uint32_t* olp = reinterpret_cast<uint32_t*>(&ol);
    float s = 0.f;
#pragma unroll
    for (int j = 0; j < 4; j++) {
        float a0 = v[2*j], a1 = v[2*j+1];
        __nv_bfloat16 h0 = __float2bfloat16(a0), h1 = __float2bfloat16(a1);
        float r0 = a0 - __bfloat162float(h0), r1 = a1 - __bfloat162float(h1);
        __nv_bfloat162 hp; hp.x = h0; hp.y = h1;
        __nv_bfloat162 lp = __floats2bfloat162_rn(r0, r1);
        ohp[j] = *reinterpret_cast<uint32_t*>(&hp);
        olp[j] = *reinterpret_cast<uint32_t*>(&lp);
        s += a0*a0 + a1*a1;
    }
    *reinterpret_cast<uint4*>(&g_eh[(size_t)row * DIMS + lane * 8]) = oh;
    *reinterpret_cast<uint4*>(&g_el[(size_t)row * DIMS + lane * 8]) = ol;
#pragma unroll
    for (int ofs = 16; ofs > 0; ofs >>= 1) s += __shfl_down_sync(0xffffffffu, s, ofs);
    if (lane == 0) g_cnorm[row] = s;
}

// ---------------- K3: split-bf16 tcgen05 coarse argmin -----------------------
// SMEM: B double buffer 128KB (hi|lo per buf), cnorm 4KB, mbar, tmem ptr.
// Merge area reuses B space after the mainloop.
static constexpr uint32_t S_B = 0, S_CN = 131072, S_MB = 135168, S_TP = 135184;
static constexpr uint32_t SMEM_NEED = 135188 + 1024 + 12;

#if HAS_TC
__device__ __forceinline__ uint32_t toff(int r, int k) {
    uint32_t lin = (uint32_t)(r >> 3) * 1024u + (uint32_t)(k >> 6) * 8192u
                 + (uint32_t)(r & 7) * 128u + (uint32_t)(k & 63) * 2u;
    return lin ^ ((lin >> 3) & 0x70u);
}
// Async-copy one 64-code tile (hi+lo, 64KB) with `nth` threads.
__device__ __forceinline__ void load_btile_async(uint32_t sbase, int tile,
                                                 int t, int nth)
{
    const __nv_bfloat16* eh = g_eh + (size_t)tile * 64 * DIMS;
    const __nv_bfloat16* el = g_el + (size_t)tile * 64 * DIMS;
    for (int c = t; c < 4096; c += nth) {
        int part = c >> 11;
        int ci = c & 2047;
        int r = ci >> 5, k = (ci & 31) << 3;
        const __nv_bfloat16* src = (part ? el : eh) + r * DIMS + k;
        uint32_t dst = sbase + (uint32_t)part * 32768u + toff(r, k);
        CP_ASYNC16(dst, src);
    }
}
#endif

__global__ __launch_bounds__(256, 1)
void coarse_kernel()
{
#if HAS_TC
    extern __shared__ char smraw[];
    uint32_t raw = smem_u32(smraw);
    uint32_t sb  = (raw + 1023u) & ~1023u;
    char* sm = smraw + (sb - raw);
    float* scn = reinterpret_cast<float*>(sm + S_CN);

    const int tid = threadIdx.x;
    const int w = tid >> 5, lane = tid & 31;
    const int sub = w & 3, half = w >> 2;
    const int rb = blockIdx.x * 128;
    const int myrow = sub * 32 + lane;          // row (0..127) this thread tracks
    const int rowg = rb + myrow;
    const uint32_t woff = ((uint32_t)sub) << 21;

    if (w == 0) TC_ALLOC(sb + S_TP, 512);
    if (tid == 0) { MBAR_INIT(sb + S_MB, 1); MBAR_INIT(sb + S_MB + 8, 1); }
#pragma unroll
    for (int i = tid; i < NCODES; i += 256) scn[i] = g_cnorm[i];
    __syncthreads();
    uint32_t tmem;
    asm volatile("ld.shared.b32 %0, [%1];" : "=r"(tmem) : "r"(sb + S_TP));

    float rn = 0.f;
    if (half == 0) {
        // warps 0-3: stage z -> TMEM (hi cols 0-127, lo cols 128-255) + rownorm
        const float* zp = &g_z[(size_t)rowg * DIMS];
#pragma unroll
        for (int ch = 0; ch < 4; ++ch) {
            float v[64];
#pragma unroll
            for (int q = 0; q < 16; ++q)
                *reinterpret_cast<float4*>(v + q * 4) =
                    *reinterpret_cast<const float4*>(zp + ch * 64 + q * 4);
            uint32_t hi[32], lo[32];
#pragma unroll
            for (int j = 0; j < 32; ++j) {
                float a0 = v[2*j], a1 = v[2*j+1];
                rn += a0*a0 + a1*a1;
                __nv_bfloat16 h0 = __float2bfloat16(a0), h1 = __float2bfloat16(a1);
                float r0 = a0 - __bfloat162float(h0), r1 = a1 - __bfloat162float(h1);
                __nv_bfloat162 hp; hp.x = h0; hp.y = h1;
                __nv_bfloat162 lp = __floats2bfloat162_rn(r0, r1);
                hi[j] = *reinterpret_cast<uint32_t*>(&hp);
                lo[j] = *reinterpret_cast<uint32_t*>(&lp);
            }
            sttm32(tmem +       ch * 32 + woff, hi);
            sttm32(tmem + 128 + ch * 32 + woff, lo);
        }
        TC_WAIT_ST();
        TC_FENCE_B();
        g_rownorm[rowg] = rn;
    } else {
        // warps 4-7: prefetch B tile 0 while staging runs
        load_btile_async(sb + S_B, 0, tid - 128, 128);
        CP_COMMIT();
    }
    __syncthreads();
    if (half == 1) rn = g_rownorm[rowg];

    float min1 = CUDART_INF_F;
    int idx1 = 0;
    int cand[NCAND]; float cdv[NCAND];
    int cnt = 0, ovf = 0;

    for (int i = 0; i < 16; ++i) {
        const int buf = i & 1;
        CP_WAIT0();
        __syncthreads();
        if (w == 0 && elect_one()) {
            TC_FENCE_A();
            uint64_t bh = make_desc(sb + S_B + (uint32_t)buf * 65536u);
            uint64_t bl = bh + 2048;   // +32768 bytes in 16B units
            uint32_t D  = tmem + 256 + buf * 64;
#pragma unroll
            for (int c = 0; c < 16; ++c) {
                uint64_t off = (uint64_t)((c >> 2) * 512 + (c & 3) * 2);
                uint32_t ah = tmem + c * 8, al = tmem + 128 + c * 8;
                mma_f16_ts(D, ah, bh + off, MMA_IDESC, c > 0);
                mma_f16_ts(D, ah, bl + off, MMA_IDESC, true);
                mma_f16_ts(D, al, bh + off, MMA_IDESC, true);
            }
            TC_COMMIT(sb + S_MB + 8 * buf);
        }
        if (i >= 1) { MBAR_WAIT(sb + S_MB + 8 * (buf ^ 1), ((i - 1) >> 1) & 1); TC_FENCE_A(); }
        if (i < 15) { load_btile_async(sb + S_B + (uint32_t)(buf ^ 1) * 65536u, i + 1, tid, 256); CP_COMMIT(); }
        if (i >= 1) {
            uint32_t regs[32];
            ldtm32(regs, tmem + 256 + (buf ^ 1) * 64 + (half << 5) + woff);
            TC_WAIT_LD();
            const int col0 = (i - 1) * 64 + (half << 5);
#pragma unroll
            for (int r = 0; r < 32; ++r) {
                int col = col0 + r;
                float d = __fadd_rn(rn, scn[col]) - 2.0f * __uint_as_float(regs[r]);
                if (d < min1) { min1 = d; idx1 = col; }
                if (d <= min1 + MARGIN) {
                    if (cnt == NCAND) {
                        int m = 0;
#pragma unroll
                        for (int k = 0; k < NCAND; k++)
                            if (cdv[k] <= min1 + MARGIN) { cand[m] = cand[k]; cdv[m] = cdv[k]; m++; }
                        cnt = m;
                    }
                    if (cnt < NCAND) { cand[cnt] = col; cdv[cnt] = d; cnt++; }
                    else ovf = 1;
                }
            }
            TC_FENCE_B();
        }
    }
    MBAR_WAIT(sb + S_MB + 8, 1);
    TC_FENCE_A();
    {
        uint32_t regs[32];
        ldtm32(regs, tmem + 256 + 64 + (half << 5) + woff);
        TC_WAIT_LD();
        const int col0 = 15 * 64 + (half << 5);
#pragma unroll
        for (int r = 0; r < 32; ++r) {
            int col = col0 + r;
            float d = __fadd_rn(rn, scn[col]) - 2.0f * __uint_as_float(regs[r]);
            if (d < min1) { min1 = d; idx1 = col; }
            if (d <= min1 + MARGIN) {
                if (cnt == NCAND) {
                    int m = 0;
#pragma unroll
                    for (int k = 0; k < NCAND; k++)
                        if (cdv[k] <= min1 + MARGIN) { cand[m] = cand[k]; cdv[m] = cdv[k]; m++; }
                    cnt = m;
                }
                if (cnt < NCAND) { cand[cnt] = col; cdv[cnt] = d; cnt++; }
                else ovf = 1;
            }
        }
    }
    TC_FENCE_B();

    // ---- merge the two column-halves per row (reuse B smem) ----
    {
        float* blk = reinterpret_cast<float*>(sm + S_B) + (myrow * 2 + half) * 32;
        blk[0] = min1;
        reinterpret_cast<int*>(blk)[1] = idx1;
        reinterpret_cast<int*>(blk)[2] = ovf ? -1 : cnt;
#pragma unroll
        for (int k = 0; k < NCAND; k++) {
            reinterpret_cast<int*>(blk)[3 + k] = (k < cnt) ? cand[k] : 0;
            blk[11 + k] = (k < cnt) ? cdv[k] : CUDART_INF_F;
        }
    }
    __syncthreads();
    if (half == 0) {
        float* A = reinterpret_cast<float*>(sm + S_B) + (myrow * 2) * 32;
        float* B = A + 32;
        float mA = A[0], mB = B[0];
        int iA = reinterpret_cast<int*>(A)[1], iB = reinterpret_cast<int*>(B)[1];
        int cA = reinterpret_cast<int*>(A)[2], cB = reinterpret_cast<int*>(B)[2];
        float gm = mA; int gi = iA;
        if (mB < gm || (mB == gm && iB < gi)) { gm = mB; gi = iB; }
        g_idx[rowg] = gi;
        if (cA < 0 || cB < 0) {
            g_ccount[rowg] = -1;
        } else {
            float thr = gm + MARGIN;
            int m = 0, over = 0;
            for (int k = 0; k < cA; k++) {
                if (A[11 + k] <= thr) {
                    if (m < NCAND) g_cands[(size_t)rowg * NCAND + m] = reinterpret_cast<int*>(A)[3 + k];
                    else over = 1;
                    m++;
                }
            }
            for (int k = 0; k < cB; k++) {
                if (B[11 + k] <= thr) {
                    if (m < NCAND) g_cands[(size_t)rowg * NCAND + m] = reinterpret_cast<int*>(B)[3 + k];
                    else over = 1;
                    m++;
                }
            }
            g_ccount[rowg] = over ? -1 : (m <= 1 ? 0 : m);
        }
    }
    __syncthreads();
    if (tid == 0) { MBAR_INVAL(sb + S_MB); MBAR_INVAL(sb + S_MB + 8); }
    __syncthreads();
    if (w == 0) { TC_RELINQ(); TC_DEALLOC(tmem, 512); }
#else
    // non-103a pass: exact rownorm + full-scan marker (never runs on GB300)
    int r = blockIdx.x * 128 + (int)threadIdx.x;
    if (threadIdx.x < 128) {
        float s = 0.f;
        for (int i = 0; i < DIMS; i++) { float v = g_z[(size_t)r * DIMS + i]; s += v * v; }
        g_rownorm[r] = s;
        g_idx[r] = 0;
        g_ccount[r] = -1;
    }
#endif
}

// ---------------- K4: exact fp32 recheck (reference rounding) ----------------
__global__ __launch_bounds__(256)
void recheck_kernel(const float* __restrict__ emb)
{
    int row  = blockIdx.x * 8 + (threadIdx.x >> 5);
    int lane = threadIdx.x & 31;
    int cnt  = g_ccount[row];
    if (cnt == 0) return;

    const float* zp = &g_z[(size_t)row * DIMS];
    float zv[8];
#pragma unroll
    for (int i = 0; i < 8; i++) zv[i] = zp[lane + 32 * i];
    float rn = g_rownorm[row];

    float bv = CUDART_INF_F;
    int   bi = 0x7fffffff;
    if (cnt > 0) {
        for (int c = 0; c < cnt; c++) {
            int idx = g_cands[(size_t)row * NCAND + c];
            const float* ep = &emb[(size_t)idx * DIMS];
            float dot = 0.f;
#pragma unroll
            for (int i = 0; i < 8; i++) dot += zv[i] * ep[lane + 32 * i];
#pragma unroll
            for (int o = 16; o > 0; o >>= 1) dot += __shfl_down_sync(0xffffffffu, dot, o);
            if (lane == 0) {
                float t = __fadd_rn(rn, g_cnorm[idx]);
                float dist = __fadd_rn(t, -__fmul_rn(2.0f, dot));
                if (dist < bv || (dist == bv && idx < bi)) { bv = dist; bi = idx; }
            }
        }
    } else {
        for (int idx = 0; idx < NCODES; idx++) {
            const float* ep = &emb[(size_t)idx * DIMS];
            float dot = 0.f;
#pragma unroll
            for (int i = 0; i < 8; i++) dot += zv[i] * ep[lane + 32 * i];
#pragma unroll
            for (int o = 16; o > 0; o >>= 1) dot += __shfl_down_sync(0xffffffffu, dot, o);
            if (lane == 0) {
                float t = __fadd_rn(rn, g_cnorm[idx]);
                float dist = __fadd_rn(t, -__fmul_rn(2.0f, dot));
                if (dist < bv) { bv = dist; bi = idx; }
            }
        }
    }
    if (lane == 0) g_idx[row] = bi;
}

// ---------------- K5: gather + per-row loss -----------------------------------
__global__ void gather_kernel(const float* __restrict__ emb,
                              float* __restrict__ outq, float* __restrict__ outi)
{
    __shared__ float ws[8];
    int row = blockIdx.x, d = threadIdx.x;
    int idx = g_idx[row];
    float e = emb[(size_t)idx * DIMS + d];
    float z = g_z[(size_t)row * DIMS + d];
    outq[(size_t)row * DIMS + d] = e;
    float diff = e - z;
    float s = diff * diff;
#pragma unroll
    for (int o = 16; o > 0; o >>= 1) s += __shfl_down_sync(0xffffffffu, s, o);
    int lane = d & 31, w = d >> 5;
    if (lane == 0) ws[w] = s;
    __syncthreads();
    if (d == 0) {
        float tot = 0.f;
#pragma unroll
        for (int i = 0; i < 8; i++) tot += ws[i];
        g_rowloss[row] = tot;
        outi[row] = (float)idx;
    }
}

// ---------------- K6: loss reduction ------------------------------------------
__global__ void loss_kernel(float* __restrict__ outl)
{
    __shared__ double sd[256];
    double s = 0.0;
    for (int i = threadIdx.x; i < M_ROWS; i += 256) s += (double)g_rowloss[i];
    sd[threadIdx.x] = s;
    __syncthreads();
    for (int o = 128; o > 0; o >>= 1) {
        if (threadIdx.x < o) sd[threadIdx.x] += sd[threadIdx.x + o];
        __syncthreads();
    }
    if (threadIdx.x == 0) outl[0] = (float)(1.25 * sd[0] / 8388608.0);
}

// ---------------- launch --------------------------------------------------------
extern "C" void kernel_launch(void* const* d_in, const int* in_sizes, int n_in,
                              void* d_out, int out_size)
{
    const float* x   = (const float*)d_in[0];
    const float* W   = (const float*)d_in[1];
    const float* b   = (const float*)d_in[2];
    const float* emb = (const float*)d_in[3];

    float* out  = (float*)d_out;
    float* outq = out;
    float* outi = out + (size_t)M_ROWS * DIMS;
    float* outl = outi + M_ROWS;

    static int smem_set = 0;
    if (!smem_set) {
        cudaFuncSetAttribute(coarse_kernel, cudaFuncAttributeMaxDynamicSharedMemorySize, SMEM_NEED);
        smem_set = 1;
    }

    dim3 g1(M_ROWS / 128, DIMS / 128);
    gemm_z_kernel<<<g1, 256>>>(x, W, b);
    conv_emb_kernel<<<NCODES / 8, 256>>>(emb);
    coarse_kernel<<<M_ROWS / 128, 256, SMEM_NEED>>>();
    recheck_kernel<<<M_ROWS / 8, 256>>>(emb);
    gather_kernel<<<M_ROWS, 256>>>(emb, outq, outi);
    loss_kernel<<<1, 256>>>(outl);
}

// round 7
// speedup vs baseline: 3.2783x; 1.0002x over previous
#include <cuda_runtime.h>
#include <cuda_bf16.h>
#include <math_constants.h>
#include <cstdint>

#define M_ROWS 32768
#define DIMS   256
#define NCODES 1024
#define NCAND  8
#define MARGIN 2.5e-4f

#if defined(__CUDA_ARCH_FEAT_SM103_ALL) || defined(__CUDA_ARCH_FEAT_SM100_ALL) || defined(__CUDA_ARCH_FEAT_SM101_ALL)
#define HAS_TC 1
#else
#define HAS_TC 0
#endif

// ---------------- device-global scratch ------------------------------------
__device__ float g_z[M_ROWS * DIMS];
__device__ __align__(16) __nv_bfloat16 g_eh[NCODES * DIMS];
__device__ __align__(16) __nv_bfloat16 g_el[NCODES * DIMS];
__device__ float g_cnorm[NCODES];
__device__ float g_rownorm[M_ROWS];
__device__ int   g_idx[M_ROWS];
__device__ float g_rowloss[M_ROWS];
__device__ int   g_cands[M_ROWS * NCAND];
__device__ int   g_ccount[M_ROWS];

// ---------------- PTX helpers ------------------------------------------------
__device__ __forceinline__ uint32_t smem_u32(const void* p) {
    uint32_t a;
    asm("{ .reg .u64 t; cvta.to.shared.u64 t, %1; cvt.u32.u64 %0, t; }" : "=r"(a) : "l"(p));
    return a;
}
#define CP_ASYNC16(s, g) asm volatile("cp.async.cg.shared.global [%0], [%1], 16;" :: "r"(s), "l"(g) : "memory")
#define CP_COMMIT()      asm volatile("cp.async.commit_group;" ::: "memory")
#define CP_WAIT0()       asm volatile("cp.async.wait_group 0;" ::: "memory")
#define MBAR_INIT(mb, c) asm volatile("mbarrier.init.shared.b64 [%0], %1;" :: "r"(mb), "r"(c) : "memory")
#define MBAR_INVAL(mb)   asm volatile("mbarrier.inval.shared.b64 [%0];" :: "r"(mb) : "memory")
#define MBAR_WAIT(mb, ph) do {                                                 \
    uint32_t _m = (mb), _p = (ph), _d;                                         \
    asm volatile("{\n\t.reg .pred p;\n\t"                                      \
        "mbarrier.try_wait.parity.acquire.cta.shared::cta.b64 p, [%1], %2;\n\t"\
        "selp.b32 %0, 1, 0, p;\n\t}" : "=r"(_d) : "r"(_m), "r"(_p) : "memory");\
    if (!_d) {                                                                 \
        asm volatile("{\n\t.reg .pred P1;\n\tWL_%=:\n\t"                       \
            "mbarrier.try_wait.parity.acquire.cta.shared::cta.b64 P1, [%0], %1, 0x989680;\n\t" \
            "@P1 bra.uni WD_%=;\n\tbra.uni WL_%=;\n\tWD_%=:\n\t}"              \
            :: "r"(_m), "r"(_p) : "memory");                                   \
    }                                                                          \
} while (0)

#if HAS_TC
__device__ __forceinline__ uint32_t elect_one() {
    uint32_t p;
    asm volatile("{\n\t.reg .pred p;\n\telect.sync _|p, 0xFFFFFFFF;\n\t"
                 "selp.b32 %0, 1, 0, p;\n\t}" : "=r"(p));
    return p;
}
#define TC_ALLOC(sa, n)  asm volatile("tcgen05.alloc.cta_group::1.sync.aligned.shared::cta.b32 [%0], %1;" :: "r"(sa), "r"(n) : "memory")
#define TC_RELINQ()      asm volatile("tcgen05.relinquish_alloc_permit.cta_group::1.sync.aligned;")
#define TC_DEALLOC(t, n) asm volatile("tcgen05.dealloc.cta_group::1.sync.aligned.b32 %0, %1;" :: "r"(t), "r"(n))
#define TC_COMMIT(mb)    asm volatile("tcgen05.commit.cta_group::1.mbarrier::arrive::one.shared::cluster.b64 [%0];" :: "r"(mb) : "memory")
#define TC_WAIT_LD()     asm volatile("tcgen05.wait::ld.sync.aligned;" ::: "memory")
#define TC_WAIT_ST()     asm volatile("tcgen05.wait::st.sync.aligned;" ::: "memory")
#define TC_FENCE_B()     asm volatile("tcgen05.fence::before_thread_sync;" ::: "memory")
#define TC_FENCE_A()     asm volatile("tcgen05.fence::after_thread_sync;" ::: "memory")

static constexpr uint64_t DESC_SW128 =
    (uint64_t(2) << 61) | (uint64_t(1) << 46) | (uint64_t(64) << 32) | (uint64_t(1) << 16);
__device__ __forceinline__ uint64_t make_desc(uint32_t a) {
    return DESC_SW128 | ((uint64_t)(a >> 4) & 0x3FFF);
}
__device__ __forceinline__ void mma_f16_ts(uint32_t d, uint32_t a, uint64_t b,
                                           uint32_t idesc, bool en) {
    uint32_t e = en ? 1u : 0u, z = 0u;
    asm volatile("{\n\t.reg .pred p;\n\tsetp.ne.u32 p, %5, 0;\n\t"
        "tcgen05.mma.cta_group::1.kind::f16 [%0], [%1], %2, %3, {%4, %4, %4, %4}, p;\n\t}"
        :: "r"(d), "r"(a), "l"(b), "r"(idesc), "r"(z), "r"(e) : "memory");
}
__device__ __forceinline__ void ldtm32(uint32_t* r, uint32_t a) {
    asm volatile("tcgen05.ld.sync.aligned.32x32b.x32.b32 "
        "{%0,%1,%2,%3,%4,%5,%6,%7,%8,%9,%10,%11,%12,%13,%14,%15,"
        "%16,%17,%18,%19,%20,%21,%22,%23,%24,%25,%26,%27,%28,%29,%30,%31}, [%32];"
        : "=r"(r[0]),"=r"(r[1]),"=r"(r[2]),"=r"(r[3]),"=r"(r[4]),"=r"(r[5]),
          "=r"(r[6]),"=r"(r[7]),"=r"(r[8]),"=r"(r[9]),"=r"(r[10]),"=r"(r[11]),
          "=r"(r[12]),"=r"(r[13]),"=r"(r[14]),"=r"(r[15]),"=r"(r[16]),"=r"(r[17]),
          "=r"(r[18]),"=r"(r[19]),"=r"(r[20]),"=r"(r[21]),"=r"(r[22]),"=r"(r[23]),
          "=r"(r[24]),"=r"(r[25]),"=r"(r[26]),"=r"(r[27]),"=r"(r[28]),"=r"(r[29]),
          "=r"(r[30]),"=r"(r[31]) : "r"(a));
}
__device__ __forceinline__ void sttm32(uint32_t a, const uint32_t* r) {
    asm volatile("tcgen05.st.sync.aligned.32x32b.x32.b32 [%0], "
        "{%1,%2,%3,%4,%5,%6,%7,%8,%9,%10,%11,%12,%13,%14,%15,%16,"
        "%17,%18,%19,%20,%21,%22,%23,%24,%25,%26,%27,%28,%29,%30,%31,%32};"
        :: "r"(a),
           "r"(r[0]),"r"(r[1]),"r"(r[2]),"r"(r[3]),"r"(r[4]),"r"(r[5]),
           "r"(r[6]),"r"(r[7]),"r"(r[8]),"r"(r[9]),"r"(r[10]),"r"(r[11]),
           "r"(r[12]),"r"(r[13]),"r"(r[14]),"r"(r[15]),"r"(r[16]),"r"(r[17]),
           "r"(r[18]),"r"(r[19]),"r"(r[20]),"r"(r[21]),"r"(r[22]),"r"(r[23]),
           "r"(r[24]),"r"(r[25]),"r"(r[26]),"r"(r[27]),"r"(r[28]),"r"(r[29]),
           "r"(r[30]),"r"(r[31]) : "memory");
}
// idesc: F32 acc(1<<4), bf16 A(1<<7)/B(1<<10), N=64(8<<17), M=128(8<<24)
static constexpr uint32_t MMA_IDESC =
    (1u << 4) | (1u << 7) | (1u << 10) | (8u << 17) | (8u << 24);
#endif // HAS_TC

// ---------------- K1: z = x @ W^T + b (fp32 exact) ---------------------------
__global__ __launch_bounds__(256, 2)
void gemm_z_kernel(const float* __restrict__ x, const float* __restrict__ W,
                   const float* __restrict__ b)
{
    __shared__ float sA[8][128], sB[8][128];
    const int tid = threadIdx.x;
    const int rb = blockIdx.x * 128, cb = blockIdx.y * 128;
    const int tx = tid & 15, ty = tid >> 4;
    const int lr = tid >> 1, lk = (tid & 1) * 4;

    float acc[8][8];
#pragma unroll
    for (int i = 0; i < 8; i++)
#pragma unroll
        for (int j = 0; j < 8; j++) acc[i][j] = 0.f;

    for (int kb = 0; kb < DIMS; kb += 8) {
        float4 av = *reinterpret_cast<const float4*>(&x[(size_t)(rb + lr) * DIMS + kb + lk]);
        float4 bv = *reinterpret_cast<const float4*>(&W[(size_t)(cb + lr) * DIMS + kb + lk]);
        sA[lk+0][lr] = av.x; sA[lk+1][lr] = av.y; sA[lk+2][lr] = av.z; sA[lk+3][lr] = av.w;
        sB[lk+0][lr] = bv.x; sB[lk+1][lr] = bv.y; sB[lk+2][lr] = bv.z; sB[lk+3][lr] = bv.w;
        __syncthreads();
#pragma unroll
        for (int kk = 0; kk < 8; kk++) {
            float4 a0 = *reinterpret_cast<float4*>(&sA[kk][ty*8]);
            float4 a1 = *reinterpret_cast<float4*>(&sA[kk][ty*8+4]);
            float4 b0 = *reinterpret_cast<float4*>(&sB[kk][tx*8]);
            float4 b1 = *reinterpret_cast<float4*>(&sB[kk][tx*8+4]);
            float a[8] = {a0.x,a0.y,a0.z,a0.w,a1.x,a1.y,a1.z,a1.w};
            float e[8] = {b0.x,b0.y,b0.z,b0.w,b1.x,b1.y,b1.z,b1.w};
#pragma unroll
            for (int i = 0; i < 8; i++)
#pragma unroll
                for (int j = 0; j < 8; j++) acc[i][j] += a[i] * e[j];
        }
        __syncthreads();
    }
#pragma unroll
    for (int i = 0; i < 8; i++) {
        int r = rb + ty * 8 + i;
#pragma unroll
        for (int j = 0; j < 8; j += 4) {
            int c = cb + tx * 8 + j;
            float4 v;
            v.x = acc[i][j+0] + b[c+0]; v.y = acc[i][j+1] + b[c+1];
            v.z = acc[i][j+2] + b[c+2]; v.w = acc[i][j+3] + b[c+3];
            *reinterpret_cast<float4*>(&g_z[(size_t)r * DIMS + c]) = v;
        }
    }
}

// ---------------- K2: emb -> split bf16 + code norms -------------------------
__global__ void conv_emb_kernel(const float* __restrict__ emb)
{
    int row = blockIdx.x * 8 + (threadIdx.x >> 5);
    int lane = threadIdx.x & 31;
    const float* p = &emb[(size_t)row * DIMS + lane * 8];
    float v[8];
    *reinterpret_cast<float4*>(v)     = *reinterpret_cast<const float4*>(p);
    *reinterpret_cast<float4*>(v + 4) = *reinterpret_cast<const float4*>(p + 4);
    uint4 oh, ol;
    uint32_t* ohp = reinterpret_cast<uint32_t*>(&oh);
    uint32_t* olp = reinterpret_cast<uint32_t*>(&ol);
    float s = 0.f;
#pragma unroll
    for (int j = 0; j < 4; j++) {
        float a0 = v[2*j], a1 = v[2*j+1];
        __nv_bfloat16 h0 = __float2bfloat16(a0), h1 = __float2bfloat16(a1);
        float r0 = a0 - __bfloat162float(h0), r1 = a1 - __bfloat162float(h1);
        __nv_bfloat162 hp; hp.x = h0; hp.y = h1;
        __nv_bfloat162 lp = __floats2bfloat162_rn(r0, r1);
        ohp[j] = *reinterpret_cast<uint32_t*>(&hp);
        olp[j] = *reinterpret_cast<uint32_t*>(&lp);
        s += a0*a0 + a1*a1;
    }
    *reinterpret_cast<uint4*>(&g_eh[(size_t)row * DIMS + lane * 8]) = oh;
    *reinterpret_cast<uint4*>(&g_el[(size_t)row * DIMS + lane * 8]) = ol;
#pragma unroll
    for (int ofs = 16; ofs > 0; ofs >>= 1) s += __shfl_down_sync(0xffffffffu, s, ofs);
    if (lane == 0) g_cnorm[row] = s;
}

// ---------------- K3: split-bf16 tcgen05 coarse argmin -----------------------
// SMEM: B double buffer 128KB (hi|lo per buf), cnorm 4KB, mbar, tmem ptr.
// Merge area reuses B space after the mainloop.
static constexpr uint32_t S_B = 0, S_CN = 131072, S_MB = 135168, S_TP = 135184;
static constexpr uint32_t SMEM_NEED = 135188 + 1024 + 12;

#if HAS_TC
__device__ __forceinline__ uint32_t toff(int r, int k) {
    uint32_t lin = (uint32_t)(r >> 3) * 1024u + (uint32_t)(k >> 6) * 8192u
                 + (uint32_t)(r & 7) * 128u + (uint32_t)(k & 63) * 2u;
    return lin ^ ((lin >> 3) & 0x70u);
}
// Async-copy one 64-code tile (hi+lo, 64KB) with `nth` threads.
__device__ __forceinline__ void load_btile_async(uint32_t sbase, int tile,
                                                 int t, int nth)
{
    const __nv_bfloat16* eh = g_eh + (size_t)tile * 64 * DIMS;
    const __nv_bfloat16* el = g_el + (size_t)tile * 64 * DIMS;
    for (int c = t; c < 4096; c += nth) {
        int part = c >> 11;
        int ci = c & 2047;
        int r = ci >> 5, k = (ci & 31) << 3;
        const __nv_bfloat16* src = (part ? el : eh) + r * DIMS + k;
        uint32_t dst = sbase + (uint32_t)part * 32768u + toff(r, k);
        CP_ASYNC16(dst, src);
    }
}
#endif

__global__ __launch_bounds__(256, 1)
void coarse_kernel()
{
#if HAS_TC
    extern __shared__ char smraw[];
    uint32_t raw = smem_u32(smraw);
    uint32_t sb  = (raw + 1023u) & ~1023u;
    char* sm = smraw + (sb - raw);
    float* scn = reinterpret_cast<float*>(sm + S_CN);

    const int tid = threadIdx.x;
    const int w = tid >> 5, lane = tid & 31;
    const int sub = w & 3, half = w >> 2;
    const int rb = blockIdx.x * 128;
    const int myrow = sub * 32 + lane;          // row (0..127) this thread tracks
    const int rowg = rb + myrow;
    const uint32_t woff = ((uint32_t)sub) << 21;

    if (w == 0) TC_ALLOC(sb + S_TP, 512);
    if (tid == 0) { MBAR_INIT(sb + S_MB, 1); MBAR_INIT(sb + S_MB + 8, 1); }
#pragma unroll
    for (int i = tid; i < NCODES; i += 256) scn[i] = g_cnorm[i];
    __syncthreads();
    uint32_t tmem;
    asm volatile("ld.shared.b32 %0, [%1];" : "=r"(tmem) : "r"(sb + S_TP));

    float rn = 0.f;
    if (half == 0) {
        // warps 0-3: stage z -> TMEM (hi cols 0-127, lo cols 128-255) + rownorm
        const float* zp = &g_z[(size_t)rowg * DIMS];
#pragma unroll
        for (int ch = 0; ch < 4; ++ch) {
            float v[64];
#pragma unroll
            for (int q = 0; q < 16; ++q)
                *reinterpret_cast<float4*>(v + q * 4) =
                    *reinterpret_cast<const float4*>(zp + ch * 64 + q * 4);
            uint32_t hi[32], lo[32];
#pragma unroll
            for (int j = 0; j < 32; ++j) {
                float a0 = v[2*j], a1 = v[2*j+1];
                rn += a0*a0 + a1*a1;
                __nv_bfloat16 h0 = __float2bfloat16(a0), h1 = __float2bfloat16(a1);
                float r0 = a0 - __bfloat162float(h0), r1 = a1 - __bfloat162float(h1);
                __nv_bfloat162 hp; hp.x = h0; hp.y = h1;
                __nv_bfloat162 lp = __floats2bfloat162_rn(r0, r1);
                hi[j] = *reinterpret_cast<uint32_t*>(&hp);
                lo[j] = *reinterpret_cast<uint32_t*>(&lp);
            }
            sttm32(tmem +       ch * 32 + woff, hi);
            sttm32(tmem + 128 + ch * 32 + woff, lo);
        }
        TC_WAIT_ST();
        TC_FENCE_B();
        g_rownorm[rowg] = rn;
    } else {
        // warps 4-7: prefetch B tile 0 while staging runs
        load_btile_async(sb + S_B, 0, tid - 128, 128);
        CP_COMMIT();
    }
    __syncthreads();
    if (half == 1) rn = g_rownorm[rowg];

    float min1 = CUDART_INF_F;
    int idx1 = 0;
    int cand[NCAND]; float cdv[NCAND];
    int cnt = 0, ovf = 0;

    for (int i = 0; i < 16; ++i) {
        const int buf = i & 1;
        CP_WAIT0();
        __syncthreads();
        if (w == 0 && elect_one()) {
            TC_FENCE_A();
            uint64_t bh = make_desc(sb + S_B + (uint32_t)buf * 65536u);
            uint64_t bl = bh + 2048;   // +32768 bytes in 16B units
            uint32_t D  = tmem + 256 + buf * 64;
#pragma unroll
            for (int c = 0; c < 16; ++c) {
                uint64_t off = (uint64_t)((c >> 2) * 512 + (c & 3) * 2);
                uint32_t ah = tmem + c * 8, al = tmem + 128 + c * 8;
                mma_f16_ts(D, ah, bh + off, MMA_IDESC, c > 0);
                mma_f16_ts(D, ah, bl + off, MMA_IDESC, true);
                mma_f16_ts(D, al, bh + off, MMA_IDESC, true);
            }
            TC_COMMIT(sb + S_MB + 8 * buf);
        }
        if (i >= 1) { MBAR_WAIT(sb + S_MB + 8 * (buf ^ 1), ((i - 1) >> 1) & 1); TC_FENCE_A(); }
        if (i < 15) { load_btile_async(sb + S_B + (uint32_t)(buf ^ 1) * 65536u, i + 1, tid, 256); CP_COMMIT(); }
        if (i >= 1) {
            uint32_t regs[32];
            ldtm32(regs, tmem + 256 + (buf ^ 1) * 64 + (half << 5) + woff);
            TC_WAIT_LD();
            const int col0 = (i - 1) * 64 + (half << 5);
#pragma unroll
            for (int r = 0; r < 32; ++r) {
                int col = col0 + r;
                float d = __fadd_rn(rn, scn[col]) - 2.0f * __uint_as_float(regs[r]);
                if (d < min1) { min1 = d; idx1 = col; }
                if (d <= min1 + MARGIN) {
                    if (cnt == NCAND) {
                        int m = 0;
#pragma unroll
                        for (int k = 0; k < NCAND; k++)
                            if (cdv[k] <= min1 + MARGIN) { cand[m] = cand[k]; cdv[m] = cdv[k]; m++; }
                        cnt = m;
                    }
                    if (cnt < NCAND) { cand[cnt] = col; cdv[cnt] = d; cnt++; }
                    else ovf = 1;
                }
            }
            TC_FENCE_B();
        }
    }
    MBAR_WAIT(sb + S_MB + 8, 1);
    TC_FENCE_A();
    {
        uint32_t regs[32];
        ldtm32(regs, tmem + 256 + 64 + (half << 5) + woff);
        TC_WAIT_LD();
        const int col0 = 15 * 64 + (half << 5);
#pragma unroll
        for (int r = 0; r < 32; ++r) {
            int col = col0 + r;
            float d = __fadd_rn(rn, scn[col]) - 2.0f * __uint_as_float(regs[r]);
            if (d < min1) { min1 = d; idx1 = col; }
            if (d <= min1 + MARGIN) {
                if (cnt == NCAND) {
                    int m = 0;
#pragma unroll
                    for (int k = 0; k < NCAND; k++)
                        if (cdv[k] <= min1 + MARGIN) { cand[m] = cand[k]; cdv[m] = cdv[k]; m++; }
                    cnt = m;
                }
                if (cnt < NCAND) { cand[cnt] = col; cdv[cnt] = d; cnt++; }
                else ovf = 1;
            }
        }
    }
    TC_FENCE_B();

    // ---- merge the two column-halves per row (reuse B smem) ----
    {
        float* blk = reinterpret_cast<float*>(sm + S_B) + (myrow * 2 + half) * 32;
        blk[0] = min1;
        reinterpret_cast<int*>(blk)[1] = idx1;
        reinterpret_cast<int*>(blk)[2] = ovf ? -1 : cnt;
#pragma unroll
        for (int k = 0; k < NCAND; k++) {
            reinterpret_cast<int*>(blk)[3 + k] = (k < cnt) ? cand[k] : 0;
            blk[11 + k] = (k < cnt) ? cdv[k] : CUDART_INF_F;
        }
    }
    __syncthreads();
    if (half == 0) {
        float* A = reinterpret_cast<float*>(sm + S_B) + (myrow * 2) * 32;
        float* B = A + 32;
        float mA = A[0], mB = B[0];
        int iA = reinterpret_cast<int*>(A)[1], iB = reinterpret_cast<int*>(B)[1];
        int cA = reinterpret_cast<int*>(A)[2], cB = reinterpret_cast<int*>(B)[2];
        float gm = mA; int gi = iA;
        if (mB < gm || (mB == gm && iB < gi)) { gm = mB; gi = iB; }
        g_idx[rowg] = gi;
        if (cA < 0 || cB < 0) {
            g_ccount[rowg] = -1;
        } else {
            float thr = gm + MARGIN;
            int m = 0, over = 0;
            for (int k = 0; k < cA; k++) {
                if (A[11 + k] <= thr) {
                    if (m < NCAND) g_cands[(size_t)rowg * NCAND + m] = reinterpret_cast<int*>(A)[3 + k];
                    else over = 1;
                    m++;
                }
            }
            for (int k = 0; k < cB; k++) {
                if (B[11 + k] <= thr) {
                    if (m < NCAND) g_cands[(size_t)rowg * NCAND + m] = reinterpret_cast<int*>(B)[3 + k];
                    else over = 1;
                    m++;
                }
            }
            g_ccount[rowg] = over ? -1 : (m <= 1 ? 0 : m);
        }
    }
    __syncthreads();
    if (tid == 0) { MBAR_INVAL(sb + S_MB); MBAR_INVAL(sb + S_MB + 8); }
    __syncthreads();
    if (w == 0) { TC_RELINQ(); TC_DEALLOC(tmem, 512); }
#else
    // non-103a pass: exact rownorm + full-scan marker (never runs on GB300)
    int r = blockIdx.x * 128 + (int)threadIdx.x;
    if (threadIdx.x < 128) {
        float s = 0.f;
        for (int i = 0; i < DIMS; i++) { float v = g_z[(size_t)r * DIMS + i]; s += v * v; }
        g_rownorm[r] = s;
        g_idx[r] = 0;
        g_ccount[r] = -1;
    }
#endif
}

// ---------------- K4: exact fp32 recheck (reference rounding) ----------------
__global__ __launch_bounds__(256)
void recheck_kernel(const float* __restrict__ emb)
{
    int row  = blockIdx.x * 8 + (threadIdx.x >> 5);
    int lane = threadIdx.x & 31;
    int cnt  = g_ccount[row];
    if (cnt == 0) return;

    const float* zp = &g_z[(size_t)row * DIMS];
    float zv[8];
#pragma unroll
    for (int i = 0; i < 8; i++) zv[i] = zp[lane + 32 * i];
    float rn = g_rownorm[row];

    float bv = CUDART_INF_F;
    int   bi = 0x7fffffff;
    if (cnt > 0) {
        for (int c = 0; c < cnt; c++) {
            int idx = g_cands[(size_t)row * NCAND + c];
            const float* ep = &emb[(size_t)idx * DIMS];
            float dot = 0.f;
#pragma unroll
            for (int i = 0; i < 8; i++) dot += zv[i] * ep[lane + 32 * i];
#pragma unroll
            for (int o = 16; o > 0; o >>= 1) dot += __shfl_down_sync(0xffffffffu, dot, o);
            if (lane == 0) {
                float t = __fadd_rn(rn, g_cnorm[idx]);
                float dist = __fadd_rn(t, -__fmul_rn(2.0f, dot));
                if (dist < bv || (dist == bv && idx < bi)) { bv = dist; bi = idx; }
            }
        }
    } else {
        for (int idx = 0; idx < NCODES; idx++) {
            const float* ep = &emb[(size_t)idx * DIMS];
            float dot = 0.f;
#pragma unroll
            for (int i = 0; i < 8; i++) dot += zv[i] * ep[lane + 32 * i];
#pragma unroll
            for (int o = 16; o > 0; o >>= 1) dot += __shfl_down_sync(0xffffffffu, dot, o);
            if (lane == 0) {
                float t = __fadd_rn(rn, g_cnorm[idx]);
                float dist = __fadd_rn(t, -__fmul_rn(2.0f, dot));
                if (dist < bv) { bv = dist; bi = idx; }
            }
        }
    }
    if (lane == 0) g_idx[row] = bi;
}

// ---------------- K5: gather + per-row loss -----------------------------------
__global__ void gather_kernel(const float* __restrict__ emb,
                              float* __restrict__ outq, float* __restrict__ outi)
{
    __shared__ float ws[8];
    int row = blockIdx.x, d = threadIdx.x;
    int idx = g_idx[row];
    float e = emb[(size_t)idx * DIMS + d];
    float z = g_z[(size_t)row * DIMS + d];
    outq[(size_t)row * DIMS + d] = e;
    float diff = e - z;
    float s = diff * diff;
#pragma unroll
    for (int o = 16; o > 0; o >>= 1) s += __shfl_down_sync(0xffffffffu, s, o);
    int lane = d & 31, w = d >> 5;
    if (lane == 0) ws[w] = s;
    __syncthreads();
    if (d == 0) {
        float tot = 0.f;
#pragma unroll
        for (int i = 0; i < 8; i++) tot += ws[i];
        g_rowloss[row] = tot;
        outi[row] = (float)idx;
    }
}

// ---------------- K6: loss reduction ------------------------------------------
__global__ void loss_kernel(float* __restrict__ outl)
{
    __shared__ double sd[256];
    double s = 0.0;
    for (int i = threadIdx.x; i < M_ROWS; i += 256) s += (double)g_rowloss[i];
    sd[threadIdx.x] = s;
    __syncthreads();
    for (int o = 128; o > 0; o >>= 1) {
        if (threadIdx.x < o) sd[threadIdx.x] += sd[threadIdx.x + o];
        __syncthreads();
    }
    if (threadIdx.x == 0) outl[0] = (float)(1.25 * sd[0] / 8388608.0);
}

// ---------------- launch --------------------------------------------------------
extern "C" void kernel_launch(void* const* d_in, const int* in_sizes, int n_in,
                              void* d_out, int out_size)
{
    const float* x   = (const float*)d_in[0];
    const float* W   = (const float*)d_in[1];
    const float* b   = (const float*)d_in[2];
    const float* emb = (const float*)d_in[3];

    float* out  = (float*)d_out;
    float* outq = out;
    float* outi = out + (size_t)M_ROWS * DIMS;
    float* outl = outi + M_ROWS;

    static int smem_set = 0;
    if (!smem_set) {
        cudaFuncSetAttribute(coarse_kernel, cudaFuncAttributeMaxDynamicSharedMemorySize, SMEM_NEED);
        smem_set = 1;
    }

    dim3 g1(M_ROWS / 128, DIMS / 128);
    gemm_z_kernel<<<g1, 256>>>(x, W, b);
    conv_emb_kernel<<<NCODES / 8, 256>>>(emb);
    coarse_kernel<<<M_ROWS / 128, 256, SMEM_NEED>>>();
    recheck_kernel<<<M_ROWS / 8, 256>>>(emb);
    gather_kernel<<<M_ROWS, 256>>>(emb, outq, outi);
    loss_kernel<<<1, 256>>>(outl);
}

// round 8
// speedup vs baseline: 4.2921x; 1.3092x over previous
#include <cuda_runtime.h>
#include <cuda_bf16.h>
#include <math_constants.h>
#include <cstdint>

#define M_ROWS 32768
#define DIMS   256
#define NCODES 1024
#define NCAND  8
#define MARGIN 2.5e-4f

#if defined(__CUDA_ARCH_FEAT_SM103_ALL) || defined(__CUDA_ARCH_FEAT_SM100_ALL) || defined(__CUDA_ARCH_FEAT_SM101_ALL)
#define HAS_TC 1
#else
#define HAS_TC 0
#endif

// ---------------- device-global scratch ------------------------------------
__device__ float g_z[M_ROWS * DIMS];
__device__ __align__(16) __nv_bfloat16 g_wh[DIMS * DIMS];
__device__ __align__(16) __nv_bfloat16 g_wm[DIMS * DIMS];
__device__ __align__(16) __nv_bfloat16 g_wl[DIMS * DIMS];
__device__ __align__(16) __nv_bfloat16 g_eh[NCODES * DIMS];
__device__ __align__(16) __nv_bfloat16 g_el[NCODES * DIMS];
__device__ float g_cnorm[NCODES];
__device__ float g_rownorm[M_ROWS];
__device__ int   g_idx[M_ROWS];
__device__ float g_rowloss[M_ROWS];
__device__ int   g_cands[M_ROWS * NCAND];
__device__ int   g_ccount[M_ROWS];

// ---------------- PTX helpers ------------------------------------------------
__device__ __forceinline__ uint32_t smem_u32(const void* p) {
    uint32_t a;
    asm("{ .reg .u64 t; cvta.to.shared.u64 t, %1; cvt.u32.u64 %0, t; }" : "=r"(a) : "l"(p));
    return a;
}
#define CP_ASYNC16(s, g) asm volatile("cp.async.cg.shared.global [%0], [%1], 16;" :: "r"(s), "l"(g) : "memory")
#define CP_COMMIT()      asm volatile("cp.async.commit_group;" ::: "memory")
#define CP_WAIT0()       asm volatile("cp.async.wait_group 0;" ::: "memory")
#define FENCE_ASYNC()    asm volatile("fence.proxy.async.shared::cta;" ::: "memory")
#define MBAR_INIT(mb, c) asm volatile("mbarrier.init.shared.b64 [%0], %1;" :: "r"(mb), "r"(c) : "memory")
#define MBAR_INVAL(mb)   asm volatile("mbarrier.inval.shared.b64 [%0];" :: "r"(mb) : "memory")
#define MBAR_WAIT(mb, ph) do {                                                 \
    uint32_t _m = (mb), _p = (ph), _d;                                         \
    asm volatile("{\n\t.reg .pred p;\n\t"                                      \
        "mbarrier.try_wait.parity.acquire.cta.shared::cta.b64 p, [%1], %2;\n\t"\
        "selp.b32 %0, 1, 0, p;\n\t}" : "=r"(_d) : "r"(_m), "r"(_p) : "memory");\
    if (!_d) {                                                                 \
        asm volatile("{\n\t.reg .pred P1;\n\tWL_%=:\n\t"                       \
            "mbarrier.try_wait.parity.acquire.cta.shared::cta.b64 P1, [%0], %1, 0x989680;\n\t" \
            "@P1 bra.uni WD_%=;\n\tbra.uni WL_%=;\n\tWD_%=:\n\t}"              \
            :: "r"(_m), "r"(_p) : "memory");                                   \
    }                                                                          \
} while (0)

#if HAS_TC
__device__ __forceinline__ uint32_t elect_one() {
    uint32_t p;
    asm volatile("{\n\t.reg .pred p;\n\telect.sync _|p, 0xFFFFFFFF;\n\t"
                 "selp.b32 %0, 1, 0, p;\n\t}" : "=r"(p));
    return p;
}
#define TC_ALLOC(sa, n)  asm volatile("tcgen05.alloc.cta_group::1.sync.aligned.shared::cta.b32 [%0], %1;" :: "r"(sa), "r"(n) : "memory")
#define TC_RELINQ()      asm volatile("tcgen05.relinquish_alloc_permit.cta_group::1.sync.aligned;")
#define TC_DEALLOC(t, n) asm volatile("tcgen05.dealloc.cta_group::1.sync.aligned.b32 %0, %1;" :: "r"(t), "r"(n))
#define TC_COMMIT(mb)    asm volatile("tcgen05.commit.cta_group::1.mbarrier::arrive::one.shared::cluster.b64 [%0];" :: "r"(mb) : "memory")
#define TC_WAIT_LD()     asm volatile("tcgen05.wait::ld.sync.aligned;" ::: "memory")
#define TC_WAIT_ST()     asm volatile("tcgen05.wait::st.sync.aligned;" ::: "memory")
#define TC_FENCE_B()     asm volatile("tcgen05.fence::before_thread_sync;" ::: "memory")
#define TC_FENCE_A()     asm volatile("tcgen05.fence::after_thread_sync;" ::: "memory")

static constexpr uint64_t DESC_SW128 =
    (uint64_t(2) << 61) | (uint64_t(1) << 46) | (uint64_t(64) << 32) | (uint64_t(1) << 16);
__device__ __forceinline__ uint64_t make_desc(uint32_t a) {
    return DESC_SW128 | ((uint64_t)(a >> 4) & 0x3FFF);
}
__device__ __forceinline__ void mma_f16_ts(uint32_t d, uint32_t a, uint64_t b,
                                           uint32_t idesc, bool en) {
    uint32_t e = en ? 1u : 0u, z = 0u;
    asm volatile("{\n\t.reg .pred p;\n\tsetp.ne.u32 p, %5, 0;\n\t"
        "tcgen05.mma.cta_group::1.kind::f16 [%0], [%1], %2, %3, {%4, %4, %4, %4}, p;\n\t}"
        :: "r"(d), "r"(a), "l"(b), "r"(idesc), "r"(z), "r"(e) : "memory");
}
__device__ __forceinline__ void mma_f16_ss(uint32_t d, uint64_t a, uint64_t b,
                                           uint32_t idesc, bool en) {
    uint32_t e = en ? 1u : 0u, z = 0u;
    asm volatile("{\n\t.reg .pred p;\n\tsetp.ne.u32 p, %5, 0;\n\t"
        "tcgen05.mma.cta_group::1.kind::f16 [%0], %1, %2, %3, {%4, %4, %4, %4}, p;\n\t}"
        :: "r"(d), "l"(a), "l"(b), "r"(idesc), "r"(z), "r"(e) : "memory");
}
__device__ __forceinline__ void ldtm32(uint32_t* r, uint32_t a) {
    asm volatile("tcgen05.ld.sync.aligned.32x32b.x32.b32 "
        "{%0,%1,%2,%3,%4,%5,%6,%7,%8,%9,%10,%11,%12,%13,%14,%15,"
        "%16,%17,%18,%19,%20,%21,%22,%23,%24,%25,%26,%27,%28,%29,%30,%31}, [%32];"
        : "=r"(r[0]),"=r"(r[1]),"=r"(r[2]),"=r"(r[3]),"=r"(r[4]),"=r"(r[5]),
          "=r"(r[6]),"=r"(r[7]),"=r"(r[8]),"=r"(r[9]),"=r"(r[10]),"=r"(r[11]),
          "=r"(r[12]),"=r"(r[13]),"=r"(r[14]),"=r"(r[15]),"=r"(r[16]),"=r"(r[17]),
          "=r"(r[18]),"=r"(r[19]),"=r"(r[20]),"=r"(r[21]),"=r"(r[22]),"=r"(r[23]),
          "=r"(r[24]),"=r"(r[25]),"=r"(r[26]),"=r"(r[27]),"=r"(r[28]),"=r"(r[29]),
          "=r"(r[30]),"=r"(r[31]) : "r"(a));
}
__device__ __forceinline__ void sttm32(uint32_t a, const uint32_t* r) {
    asm volatile("tcgen05.st.sync.aligned.32x32b.x32.b32 [%0], "
        "{%1,%2,%3,%4,%5,%6,%7,%8,%9,%10,%11,%12,%13,%14,%15,%16,"
        "%17,%18,%19,%20,%21,%22,%23,%24,%25,%26,%27,%28,%29,%30,%31,%32};"
        :: "r"(a),
           "r"(r[0]),"r"(r[1]),"r"(r[2]),"r"(r[3]),"r"(r[4]),"r"(r[5]),
           "r"(r[6]),"r"(r[7]),"r"(r[8]),"r"(r[9]),"r"(r[10]),"r"(r[11]),
           "r"(r[12]),"r"(r[13]),"r"(r[14]),"r"(r[15]),"r"(r[16]),"r"(r[17]),
           "r"(r[18]),"r"(r[19]),"r"(r[20]),"r"(r[21]),"r"(r[22]),"r"(r[23]),
           "r"(r[24]),"r"(r[25]),"r"(r[26]),"r"(r[27]),"r"(r[28]),"r"(r[29]),
           "r"(r[30]),"r"(r[31]) : "memory");
}
static constexpr uint32_t MMA_IDESC =   // coarse: N=64
    (1u << 4) | (1u << 7) | (1u << 10) | (8u << 17) | (8u << 24);
static constexpr uint32_t IDESC_G =     // gemm: N=256
    (1u << 4) | (1u << 7) | (1u << 10) | (32u << 17) | (8u << 24);
#endif // HAS_TC

__device__ __forceinline__ void split3(float a, __nv_bfloat16& h, __nv_bfloat16& m,
                                       __nv_bfloat16& l) {
    h = __float2bfloat16(a);
    float r = a - __bfloat162float(h);
    m = __float2bfloat16(r);
    l = __float2bfloat16(r - __bfloat162float(m));
}
// swizzled byte offset in a (rows x 64) bf16 K-major SW128 tile
__device__ __forceinline__ uint32_t toff(int r, int k) {
    uint32_t lin = (uint32_t)(r >> 3) * 1024u + (uint32_t)(k >> 6) * 8192u
                 + (uint32_t)(r & 7) * 128u + (uint32_t)(k & 63) * 2u;
    return lin ^ ((lin >> 3) & 0x70u);
}

// ---------------- K0: W -> 3-way bf16 split ---------------------------------
__global__ void conv_w_kernel(const float* __restrict__ W)
{
    size_t base = ((size_t)blockIdx.x * 256 + threadIdx.x) * 8;
    float v[8];
    *reinterpret_cast<float4*>(v)     = *reinterpret_cast<const float4*>(W + base);
    *reinterpret_cast<float4*>(v + 4) = *reinterpret_cast<const float4*>(W + base + 4);
    __nv_bfloat16 h[8], m[8], l[8];
#pragma unroll
    for (int j = 0; j < 8; j++) split3(v[j], h[j], m[j], l[j]);
    *reinterpret_cast<uint4*>(&g_wh[base]) = *reinterpret_cast<uint4*>(h);
    *reinterpret_cast<uint4*>(&g_wm[base]) = *reinterpret_cast<uint4*>(m);
    *reinterpret_cast<uint4*>(&g_wl[base]) = *reinterpret_cast<uint4*>(l);
}

// ---------------- K1: z = x @ W^T + b  (tcgen05, 3-split bf16) ---------------
static constexpr uint32_t G_A = 0;           // 2 buf x 3 splits x 16KB = 96KB
static constexpr uint32_t G_B = 98304;       // 3 splits x 32KB = 96KB
static constexpr uint32_t G_BIAS = 196608;
static constexpr uint32_t G_MB = 197632, G_TP = 197640;
static constexpr uint32_t GSMEM_NEED = 197644 + 1040;

__global__ __launch_bounds__(256, 1)
void gemm_z_tc(const float* __restrict__ x, const float* __restrict__ W,
               const float* __restrict__ bias)
{
#if HAS_TC
    extern __shared__ char smraw[];
    uint32_t raw = smem_u32(smraw);
    uint32_t sb  = (raw + 1023u) & ~1023u;
    char* sm = smraw + (sb - raw);
    float* sbias = reinterpret_cast<float*>(sm + G_BIAS);

    const int tid = threadIdx.x;
    const int rb  = blockIdx.x * 128;

    if (tid < 32) TC_ALLOC(sb + G_TP, 256);
    if (tid == 0) MBAR_INIT(sb + G_MB, 1);
    sbias[tid] = bias[tid];
    __syncthreads();
    uint32_t tmem;
    asm volatile("ld.shared.b32 %0, [%1];" : "=r"(tmem) : "r"(sb + G_TP));

    // stage A chunk 0 (load x fp32, split, swizzled store)
#pragma unroll
    for (int g = tid; g < 1024; g += 256) {
        int r = g >> 3, k8 = (g & 7) << 3;
        const float* src = x + (size_t)(rb + r) * DIMS + k8;
        float v[8];
        *reinterpret_cast<float4*>(v)     = *reinterpret_cast<const float4*>(src);
        *reinterpret_cast<float4*>(v + 4) = *reinterpret_cast<const float4*>(src + 4);
        __nv_bfloat16 h[8], m[8], l[8];
#pragma unroll
        for (int j = 0; j < 8; j++) split3(v[j], h[j], m[j], l[j]);
        uint32_t o = toff(r, k8);
        *reinterpret_cast<uint4*>(sm + G_A + o)         = *reinterpret_cast<uint4*>(h);
        *reinterpret_cast<uint4*>(sm + G_A + 16384 + o) = *reinterpret_cast<uint4*>(m);
        *reinterpret_cast<uint4*>(sm + G_A + 32768 + o) = *reinterpret_cast<uint4*>(l);
    }
    FENCE_ASYNC();

    for (int ch = 0; ch < 4; ++ch) {
        // load B (W splits) for this K-chunk
        for (int c = tid; c < 6144; c += 256) {
            int s = c >> 11, ci = c & 2047;
            int r = ci >> 3, k8 = (ci & 7) << 3;
            const __nv_bfloat16* src =
                (s == 0 ? g_wh : s == 1 ? g_wm : g_wl) + (size_t)r * DIMS + ch * 64 + k8;
            CP_ASYNC16(sb + G_B + (uint32_t)s * 32768u + toff(r, k8), src);
        }
        CP_COMMIT(); CP_WAIT0();
        __syncthreads();

        if (tid < 32 && elect_one()) {
            TC_FENCE_A();
            uint64_t A0 = make_desc(sb + G_A + (uint32_t)(ch & 1) * 49152u);
            uint64_t A1 = A0 + 1024, A2 = A0 + 2048;
            uint64_t B0 = make_desc(sb + G_B);
            uint64_t B1 = B0 + 2048, B2 = B0 + 4096;
#pragma unroll
            for (int kk = 0; kk < 4; ++kk) {
                uint64_t off = (uint64_t)(kk * 2);
                mma_f16_ss(tmem, A0 + off, B0 + off, IDESC_G, !(ch == 0 && kk == 0));
                mma_f16_ss(tmem, A0 + off, B1 + off, IDESC_G, true);
                mma_f16_ss(tmem, A1 + off, B0 + off, IDESC_G, true);
                mma_f16_ss(tmem, A1 + off, B1 + off, IDESC_G, true);
                mma_f16_ss(tmem, A0 + off, B2 + off, IDESC_G, true);
                mma_f16_ss(tmem, A2 + off, B0 + off, IDESC_G, true);
            }
            TC_COMMIT(sb + G_MB);
        }
        // stage A for next chunk while MMAs run
        if (ch < 3) {
            uint32_t abase = G_A + (uint32_t)((ch + 1) & 1) * 49152u;
#pragma unroll
            for (int g = tid; g < 1024; g += 256) {
                int r = g >> 3, k8 = (g & 7) << 3;
                const float* src = x + (size_t)(rb + r) * DIMS + (ch + 1) * 64 + k8;
                float v[8];
                *reinterpret_cast<float4*>(v)     = *reinterpret_cast<const float4*>(src);
                *reinterpret_cast<float4*>(v + 4) = *reinterpret_cast<const float4*>(src + 4);
                __nv_bfloat16 h[8], m[8], l[8];
#pragma unroll
                for (int j = 0; j < 8; j++) split3(v[j], h[j], m[j], l[j]);
                uint32_t o = toff(r, k8);
                *reinterpret_cast<uint4*>(sm + abase + o)         = *reinterpret_cast<uint4*>(h);
                *reinterpret_cast<uint4*>(sm + abase + 16384 + o) = *reinterpret_cast<uint4*>(m);
                *reinterpret_cast<uint4*>(sm + abase + 32768 + o) = *reinterpret_cast<uint4*>(l);
            }
            FENCE_ASYNC();
        }
        MBAR_WAIT(sb + G_MB, ch & 1);
        __syncthreads();
    }
    TC_FENCE_A();

    // epilogue: D[128 x 256] fp32 + bias -> g_z
    const int sub = (tid >> 5) & 3, half = tid >> 7, lane = tid & 31;
    const int row = rb + sub * 32 + lane;
    const uint32_t woff = ((uint32_t)sub) << 21;
#pragma unroll
    for (int q = 0; q < 4; ++q) {
        uint32_t regs[32];
        ldtm32(regs, tmem + half * 128 + q * 32 + woff);
        TC_WAIT_LD();
        int c0 = half * 128 + q * 32;
#pragma unroll
        for (int j = 0; j < 32; j += 4) {
            float4 v;
            v.x = __uint_as_float(regs[j+0]) + sbias[c0+j+0];
            v.y = __uint_as_float(regs[j+1]) + sbias[c0+j+1];
            v.z = __uint_as_float(regs[j+2]) + sbias[c0+j+2];
            v.w = __uint_as_float(regs[j+3]) + sbias[c0+j+3];
            *reinterpret_cast<float4*>(&g_z[(size_t)row * DIMS + c0 + j]) = v;
        }
    }
    TC_FENCE_B();
    __syncthreads();
    if (tid == 0) MBAR_INVAL(sb + G_MB);
    __syncthreads();
    if (tid < 32) { TC_RELINQ(); TC_DEALLOC(tmem, 256); }
#else
    // fallback pass (never runs on GB300): exact fp32
    int tid = threadIdx.x, rb = blockIdx.x * 128;
    for (int o = tid; o < 128 * DIMS; o += 256) {
        int r = rb + (o >> 8), c = o & 255;
        float acc = 0.f;
        for (int k = 0; k < DIMS; k++)
            acc += x[(size_t)r * DIMS + k] * W[(size_t)c * DIMS + k];
        g_z[(size_t)r * DIMS + c] = acc + bias[c];
    }
#endif
}

// ---------------- K2: emb -> split bf16 + code norms -------------------------
__global__ void conv_emb_kernel(const float* __restrict__ emb)
{
    int row = blockIdx.x * 8 + (threadIdx.x >> 5);
    int lane = threadIdx.x & 31;
    const float* p = &emb[(size_t)row * DIMS + lane * 8];
    float v[8];
    *reinterpret_cast<float4*>(v)     = *reinterpret_cast<const float4*>(p);
    *reinterpret_cast<float4*>(v + 4) = *reinterpret_cast<const float4*>(p + 4);
    uint4 oh, ol;
    uint32_t* ohp = reinterpret_cast<uint32_t*>(&oh);
    uint32_t* olp = reinterpret_cast<uint32_t*>(&ol);
    float s = 0.f;
#pragma unroll
    for (int j = 0; j < 4; j++) {
        float a0 = v[2*j], a1 = v[2*j+1];
        __nv_bfloat16 h0 = __float2bfloat16(a0), h1 = __float2bfloat16(a1);
        float r0 = a0 - __bfloat162float(h0), r1 = a1 - __bfloat162float(h1);
        __nv_bfloat162 hp; hp.x = h0; hp.y = h1;
        __nv_bfloat162 lp = __floats2bfloat162_rn(r0, r1);
        ohp[j] = *reinterpret_cast<uint32_t*>(&hp);
        olp[j] = *reinterpret_cast<uint32_t*>(&lp);
        s += a0*a0 + a1*a1;
    }
    *reinterpret_cast<uint4*>(&g_eh[(size_t)row * DIMS + lane * 8]) = oh;
    *reinterpret_cast<uint4*>(&g_el[(size_t)row * DIMS + lane * 8]) = ol;
#pragma unroll
    for (int ofs = 16; ofs > 0; ofs >>= 1) s += __shfl_down_sync(0xffffffffu, s, ofs);
    if (lane == 0) g_cnorm[row] = s;
}

// ---------------- K3: split-bf16 tcgen05 coarse argmin (unchanged R6) --------
static constexpr uint32_t S_B = 0, S_CN = 131072, S_MB = 135168, S_TP = 135184;
static constexpr uint32_t SMEM_NEED = 135188 + 1024 + 12;

#if HAS_TC
__device__ __forceinline__ void load_btile_async(uint32_t sbase, int tile,
                                                 int t, int nth)
{
    const __nv_bfloat16* eh = g_eh + (size_t)tile * 64 * DIMS;
    const __nv_bfloat16* el = g_el + (size_t)tile * 64 * DIMS;
    for (int c = t; c < 4096; c += nth) {
        int part = c >> 11;
        int ci = c & 2047;
        int r = ci >> 5, k = (ci & 31) << 3;
        const __nv_bfloat16* src = (part ? el : eh) + r * DIMS + k;
        CP_ASYNC16(sbase + (uint32_t)part * 32768u + toff(r, k), src);
    }
}
#endif

__global__ __launch_bounds__(256, 1)
void coarse_kernel()
{
#if HAS_TC
    extern __shared__ char smraw[];
    uint32_t raw = smem_u32(smraw);
    uint32_t sb  = (raw + 1023u) & ~1023u;
    char* sm = smraw + (sb - raw);
    float* scn = reinterpret_cast<float*>(sm + S_CN);

    const int tid = threadIdx.x;
    const int w = tid >> 5, lane = tid & 31;
    const int sub = w & 3, half = w >> 2;
    const int rb = blockIdx.x * 128;
    const int myrow = sub * 32 + lane;
    const int rowg = rb + myrow;
    const uint32_t woff = ((uint32_t)sub) << 21;

    if (w == 0) TC_ALLOC(sb + S_TP, 512);
    if (tid == 0) { MBAR_INIT(sb + S_MB, 1); MBAR_INIT(sb + S_MB + 8, 1); }
#pragma unroll
    for (int i = tid; i < NCODES; i += 256) scn[i] = g_cnorm[i];
    __syncthreads();
    uint32_t tmem;
    asm volatile("ld.shared.b32 %0, [%1];" : "=r"(tmem) : "r"(sb + S_TP));

    float rn = 0.f;
    if (half == 0) {
        const float* zp = &g_z[(size_t)rowg * DIMS];
#pragma unroll
        for (int ch = 0; ch < 4; ++ch) {
            float v[64];
#pragma unroll
            for (int q = 0; q < 16; ++q)
                *reinterpret_cast<float4*>(v + q * 4) =
                    *reinterpret_cast<const float4*>(zp + ch * 64 + q * 4);
            uint32_t hi[32], lo[32];
#pragma unroll
            for (int j = 0; j < 32; ++j) {
                float a0 = v[2*j], a1 = v[2*j+1];
                rn += a0*a0 + a1*a1;
                __nv_bfloat16 h0 = __float2bfloat16(a0), h1 = __float2bfloat16(a1);
                float r0 = a0 - __bfloat162float(h0), r1 = a1 - __bfloat162float(h1);
                __nv_bfloat162 hp; hp.x = h0; hp.y = h1;
                __nv_bfloat162 lp = __floats2bfloat162_rn(r0, r1);
                hi[j] = *reinterpret_cast<uint32_t*>(&hp);
                lo[j] = *reinterpret_cast<uint32_t*>(&lp);
            }
            sttm32(tmem +       ch * 32 + woff, hi);
            sttm32(tmem + 128 + ch * 32 + woff, lo);
        }
        TC_WAIT_ST();
        TC_FENCE_B();
        g_rownorm[rowg] = rn;
    } else {
        load_btile_async(sb + S_B, 0, tid - 128, 128);
        CP_COMMIT();
    }
    __syncthreads();
    if (half == 1) rn = g_rownorm[rowg];

    float min1 = CUDART_INF_F;
    int idx1 = 0;
    int cand[NCAND]; float cdv[NCAND];
    int cnt = 0, ovf = 0;

    for (int i = 0; i < 16; ++i) {
        const int buf = i & 1;
        CP_WAIT0();
        __syncthreads();
        if (w == 0 && elect_one()) {
            TC_FENCE_A();
            uint64_t bh = make_desc(sb + S_B + (uint32_t)buf * 65536u);
            uint64_t bl = bh + 2048;
            uint32_t D  = tmem + 256 + buf * 64;
#pragma unroll
            for (int c = 0; c < 16; ++c) {
                uint64_t off = (uint64_t)((c >> 2) * 512 + (c & 3) * 2);
                uint32_t ah = tmem + c * 8, al = tmem + 128 + c * 8;
                mma_f16_ts(D, ah, bh + off, MMA_IDESC, c > 0);
                mma_f16_ts(D, ah, bl + off, MMA_IDESC, true);
                mma_f16_ts(D, al, bh + off, MMA_IDESC, true);
            }
            TC_COMMIT(sb + S_MB + 8 * buf);
        }
        if (i >= 1) { MBAR_WAIT(sb + S_MB + 8 * (buf ^ 1), ((i - 1) >> 1) & 1); TC_FENCE_A(); }
        if (i < 15) { load_btile_async(sb + S_B + (uint32_t)(buf ^ 1) * 65536u, i + 1, tid, 256); CP_COMMIT(); }
        if (i >= 1) {
            uint32_t regs[32];
            ldtm32(regs, tmem + 256 + (buf ^ 1) * 64 + (half << 5) + woff);
            TC_WAIT_LD();
            const int col0 = (i - 1) * 64 + (half << 5);
#pragma unroll
            for (int r = 0; r < 32; ++r) {
                int col = col0 + r;
                float d = __fadd_rn(rn, scn[col]) - 2.0f * __uint_as_float(regs[r]);
                if (d < min1) { min1 = d; idx1 = col; }
                if (d <= min1 + MARGIN) {
                    if (cnt == NCAND) {
                        int m = 0;
#pragma unroll
                        for (int k = 0; k < NCAND; k++)
                            if (cdv[k] <= min1 + MARGIN) { cand[m] = cand[k]; cdv[m] = cdv[k]; m++; }
                        cnt = m;
                    }
                    if (cnt < NCAND) { cand[cnt] = col; cdv[cnt] = d; cnt++; }
                    else ovf = 1;
                }
            }
            TC_FENCE_B();
        }
    }
    MBAR_WAIT(sb + S_MB + 8, 1);
    TC_FENCE_A();
    {
        uint32_t regs[32];
        ldtm32(regs, tmem + 256 + 64 + (half << 5) + woff);
        TC_WAIT_LD();
        const int col0 = 15 * 64 + (half << 5);
#pragma unroll
        for (int r = 0; r < 32; ++r) {
            int col = col0 + r;
            float d = __fadd_rn(rn, scn[col]) - 2.0f * __uint_as_float(regs[r]);
            if (d < min1) { min1 = d; idx1 = col; }
            if (d <= min1 + MARGIN) {
                if (cnt == NCAND) {
                    int m = 0;
#pragma unroll
                    for (int k = 0; k < NCAND; k++)
                        if (cdv[k] <= min1 + MARGIN) { cand[m] = cand[k]; cdv[m] = cdv[k]; m++; }
                    cnt = m;
                }
                if (cnt < NCAND) { cand[cnt] = col; cdv[cnt] = d; cnt++; }
                else ovf = 1;
            }
        }
    }
    TC_FENCE_B();

    {
        float* blk = reinterpret_cast<float*>(sm + S_B) + (myrow * 2 + half) * 32;
        blk[0] = min1;
        reinterpret_cast<int*>(blk)[1] = idx1;
        reinterpret_cast<int*>(blk)[2] = ovf ? -1 : cnt;
#pragma unroll
        for (int k = 0; k < NCAND; k++) {
            reinterpret_cast<int*>(blk)[3 + k] = (k < cnt) ? cand[k] : 0;
            blk[11 + k] = (k < cnt) ? cdv[k] : CUDART_INF_F;
        }
    }
    __syncthreads();
    if (half == 0) {
        float* A = reinterpret_cast<float*>(sm + S_B) + (myrow * 2) * 32;
        float* B = A + 32;
        float mA = A[0], mB = B[0];
        int iA = reinterpret_cast<int*>(A)[1], iB = reinterpret_cast<int*>(B)[1];
        int cA = reinterpret_cast<int*>(A)[2], cB = reinterpret_cast<int*>(B)[2];
        float gm = mA; int gi = iA;
        if (mB < gm || (mB == gm && iB < gi)) { gm = mB; gi = iB; }
        g_idx[rowg] = gi;
        if (cA < 0 || cB < 0) {
            g_ccount[rowg] = -1;
        } else {
            float thr = gm + MARGIN;
            int m = 0, over = 0;
            for (int k = 0; k < cA; k++) {
                if (A[11 + k] <= thr) {
                    if (m < NCAND) g_cands[(size_t)rowg * NCAND + m] = reinterpret_cast<int*>(A)[3 + k];
                    else over = 1;
                    m++;
                }
            }
            for (int k = 0; k < cB; k++) {
                if (B[11 + k] <= thr) {
                    if (m < NCAND) g_cands[(size_t)rowg * NCAND + m] = reinterpret_cast<int*>(B)[3 + k];
                    else over = 1;
                    m++;
                }
            }
            g_ccount[rowg] = over ? -1 : (m <= 1 ? 0 : m);
        }
    }
    __syncthreads();
    if (tid == 0) { MBAR_INVAL(sb + S_MB); MBAR_INVAL(sb + S_MB + 8); }
    __syncthreads();
    if (w == 0) { TC_RELINQ(); TC_DEALLOC(tmem, 512); }
#else
    int r = blockIdx.x * 128 + (int)threadIdx.x;
    if (threadIdx.x < 128) {
        float s = 0.f;
        for (int i = 0; i < DIMS; i++) { float v = g_z[(size_t)r * DIMS + i]; s += v * v; }
        g_rownorm[r] = s;
        g_idx[r] = 0;
        g_ccount[r] = -1;
    }
#endif
}

// ---------------- K4: exact fp32 recheck --------------------------------------
__global__ __launch_bounds__(256)
void recheck_kernel(const float* __restrict__ emb)
{
    int row  = blockIdx.x * 8 + (threadIdx.x >> 5);
    int lane = threadIdx.x & 31;
    int cnt  = g_ccount[row];
    if (cnt == 0) return;

    const float* zp = &g_z[(size_t)row * DIMS];
    float zv[8];
#pragma unroll
    for (int i = 0; i < 8; i++) zv[i] = zp[lane + 32 * i];
    float rn = g_rownorm[row];

    float bv = CUDART_INF_F;
    int   bi = 0x7fffffff;
    if (cnt > 0) {
        for (int c = 0; c < cnt; c++) {
            int idx = g_cands[(size_t)row * NCAND + c];
            const float* ep = &emb[(size_t)idx * DIMS];
            float dot = 0.f;
#pragma unroll
            for (int i = 0; i < 8; i++) dot += zv[i] * ep[lane + 32 * i];
#pragma unroll
            for (int o = 16; o > 0; o >>= 1) dot += __shfl_down_sync(0xffffffffu, dot, o);
            if (lane == 0) {
                float t = __fadd_rn(rn, g_cnorm[idx]);
                float dist = __fadd_rn(t, -__fmul_rn(2.0f, dot));
                if (dist < bv || (dist == bv && idx < bi)) { bv = dist; bi = idx; }
            }
        }
    } else {
        for (int idx = 0; idx < NCODES; idx++) {
            const float* ep = &emb[(size_t)idx * DIMS];
            float dot = 0.f;
#pragma unroll
            for (int i = 0; i < 8; i++) dot += zv[i] * ep[lane + 32 * i];
#pragma unroll
            for (int o = 16; o > 0; o >>= 1) dot += __shfl_down_sync(0xffffffffu, dot, o);
            if (lane == 0) {
                float t = __fadd_rn(rn, g_cnorm[idx]);
                float dist = __fadd_rn(t, -__fmul_rn(2.0f, dot));
                if (dist < bv) { bv = dist; bi = idx; }
            }
        }
    }
    if (lane == 0) g_idx[row] = bi;
}

// ---------------- K5: gather + per-row loss -----------------------------------
__global__ void gather_kernel(const float* __restrict__ emb,
                              float* __restrict__ outq, float* __restrict__ outi)
{
    __shared__ float ws[8];
    int row = blockIdx.x, d = threadIdx.x;
    int idx = g_idx[row];
    float e = emb[(size_t)idx * DIMS + d];
    float z = g_z[(size_t)row * DIMS + d];
    outq[(size_t)row * DIMS + d] = e;
    float diff = e - z;
    float s = diff * diff;
#pragma unroll
    for (int o = 16; o > 0; o >>= 1) s += __shfl_down_sync(0xffffffffu, s, o);
    int lane = d & 31, w = d >> 5;
    if (lane == 0) ws[w] = s;
    __syncthreads();
    if (d == 0) {
        float tot = 0.f;
#pragma unroll
        for (int i = 0; i < 8; i++) tot += ws[i];
        g_rowloss[row] = tot;
        outi[row] = (float)idx;
    }
}

// ---------------- K6: loss reduction ------------------------------------------
__global__ void loss_kernel(float* __restrict__ outl)
{
    __shared__ double sd[256];
    double s = 0.0;
    for (int i = threadIdx.x; i < M_ROWS; i += 256) s += (double)g_rowloss[i];
    sd[threadIdx.x] = s;
    __syncthreads();
    for (int o = 128; o > 0; o >>= 1) {
        if (threadIdx.x < o) sd[threadIdx.x] += sd[threadIdx.x + o];
        __syncthreads();
    }
    if (threadIdx.x == 0) outl[0] = (float)(1.25 * sd[0] / 8388608.0);
}

// ---------------- launch --------------------------------------------------------
extern "C" void kernel_launch(void* const* d_in, const int* in_sizes, int n_in,
                              void* d_out, int out_size)
{
    const float* x   = (const float*)d_in[0];
    const float* W   = (const float*)d_in[1];
    const float* b   = (const float*)d_in[2];
    const float* emb = (const float*)d_in[3];

    float* out  = (float*)d_out;
    float* outq = out;
    float* outi = out + (size_t)M_ROWS * DIMS;
    float* outl = outi + M_ROWS;

    static int smem_set = 0;
    if (!smem_set) {
        cudaFuncSetAttribute(coarse_kernel, cudaFuncAttributeMaxDynamicSharedMemorySize, SMEM_NEED);
        cudaFuncSetAttribute(gemm_z_tc, cudaFuncAttributeMaxDynamicSharedMemorySize, GSMEM_NEED);
        smem_set = 1;
    }

    conv_w_kernel<<<32, 256>>>(W);
    conv_emb_kernel<<<NCODES / 8, 256>>>(emb);
    gemm_z_tc<<<M_ROWS / 128, 256, GSMEM_NEED>>>(x, W, b);
    coarse_kernel<<<M_ROWS / 128, 256, SMEM_NEED>>>();
    recheck_kernel<<<M_ROWS / 8, 256>>>(emb);
    gather_kernel<<<M_ROWS, 256>>>(emb, outq, outi);
    loss_kernel<<<1, 256>>>(outl);
}